// round 5
// baseline (speedup 1.0000x reference)
#include <cuda_runtime.h>
#include <math.h>

#define C_DIM 1024
#define NQ 10            // gated queries (ref has NQ+1 = 11 query rows)
#define NP 5             // q-pairs
#define MAXN 100000
#define K1_RPW 4         // rows per warp per tile
#define K1_WARPS 8
#define K1_RPB (K1_RPW * K1_WARPS)   // 32 rows per tile
#define K1_GRID 296                  // persistent, 2 CTAs/SM
#define K2_TILE 128
#define K2_GRID 592                  // persistent, 4 CTAs/SM

typedef unsigned long long u64;

// ---- scratch (static device memory; no allocations) ----
__device__ u64   g_Qp[NP * C_DIM];                    // packed q-pair diffs
__device__ float g_logits[(size_t)NQ * MAXN];         // [q][n], 4 MB
__device__ float g_bmax[(size_t)K1_GRID * NQ];        // per-block max partials
__device__ float g_M[NQ];                             // per-q max logit
__device__ float g_Z[NQ];                             // per-q softmax denom
__device__ float g_partial[(size_t)K2_GRID * C_DIM];  // pass-2 partials
__device__ float g_pooled[C_DIM];

// ---- packed f32x2 helpers ----
__device__ __forceinline__ u64 f2fma(u64 a, u64 b, u64 c) {
    u64 d;
    asm("fma.rn.f32x2 %0, %1, %2, %3;" : "=l"(d) : "l"(a), "l"(b), "l"(c));
    return d;
}
__device__ __forceinline__ u64 f2add(u64 a, u64 b) {
    u64 d;
    asm("add.rn.f32x2 %0, %1, %2;" : "=l"(d) : "l"(a), "l"(b));
    return d;
}
__device__ __forceinline__ u64 fdup(float x) {
    u64 d;
    asm("mov.b64 %0, {%1, %1};" : "=l"(d) : "f"(x));
    return d;
}
__device__ __forceinline__ u64 fpack(float lo, float hi) {
    u64 d;
    asm("mov.b64 %0, {%1, %2};" : "=l"(d) : "f"(lo), "f"(hi));
    return d;
}
__device__ __forceinline__ float f2lo(u64 v) { return __uint_as_float((unsigned)v); }
__device__ __forceinline__ float f2hi(u64 v) { return __uint_as_float((unsigned)(v >> 32)); }
__device__ __forceinline__ u64 shfl_xor64(u64 v, int off) {
    unsigned lo = (unsigned)v, hi = (unsigned)(v >> 32);
    lo = __shfl_xor_sync(0xffffffffu, lo, off);
    hi = __shfl_xor_sync(0xffffffffu, hi, off);
    return (u64)lo | ((u64)hi << 32);
}

// ============================================================
// K0: normalize Q rows, build packed Qp pairs; init Z/pooled
// ============================================================
__global__ void k0_prep(const float* __restrict__ Q) {
    __shared__ float s_inv[NQ + 1];
    __shared__ float s_red[128];
    int t = threadIdx.x;
    for (int q = 0; q < NQ + 1; q++) {
        float ss = 0.f;
        for (int c = t; c < C_DIM; c += 128) {
            float v = Q[q * C_DIM + c];
            ss = fmaf(v, v, ss);
        }
        s_red[t] = ss;
        __syncthreads();
        for (int s = 64; s > 0; s >>= 1) {
            if (t < s) s_red[t] += s_red[t + s];
            __syncthreads();
        }
        if (t == 0) s_inv[q] = 1.0f / fmaxf(sqrtf(s_red[0]), 1e-12f);
        __syncthreads();
    }
    float invL = s_inv[NQ];
    for (int c = t; c < C_DIM; c += 128) {
        float ql = Q[NQ * C_DIM + c] * invL;
#pragma unroll
        for (int p = 0; p < NP; p++) {
            float lo = Q[(2 * p) * C_DIM + c] * s_inv[2 * p] - ql;
            float hi = Q[(2 * p + 1) * C_DIM + c] * s_inv[2 * p + 1] - ql;
            g_Qp[p * C_DIM + c] = fpack(lo, hi);
        }
    }
    if (t < NQ) g_Z[t] = 0.f;
    for (int c = t; c < C_DIM; c += 128) g_pooled[c] = 0.f;
}

// ============================================================
// K1: logits[q][n] = 100 * (Qd[q] . X[n]) / max(||X[n]||, eps)
// q-pair packed accumulators (40 regs), 2 CTAs/SM (16 warps),
// lane owns cols {2l,2l+1,2l+64,2l+65} per 128-chunk (conflict-free)
// ============================================================
__global__ __launch_bounds__(256, 2) void k1_logits(const float* __restrict__ X,
                                                    int N, int ntiles) {
    __shared__ u64 s_qp[NP * C_DIM];            // 40 KB
    __shared__ float s_l[NQ][K1_RPB];
    __shared__ float s_wmax[K1_WARPS][NQ];
    int t = threadIdx.x;
    int warp = t >> 5, lane = t & 31;
    for (int i = t; i < NP * C_DIM; i += 256) s_qp[i] = g_Qp[i];
    if (t < K1_WARPS * NQ) ((float*)s_wmax)[t] = -1e30f;
    __syncthreads();

    for (int tile = blockIdx.x; tile < ntiles; tile += gridDim.x) {
        int row0 = tile * K1_RPB + warp * K1_RPW;
        int ro[K1_RPW];
#pragma unroll
        for (int j = 0; j < K1_RPW; j++) {
            int r = row0 + j;
            if (r > N - 1) r = N - 1;
            ro[j] = r * C_DIM + 2 * lane;
        }

        u64 acc[K1_RPW][NP];
        float nacc[K1_RPW];
#pragma unroll
        for (int j = 0; j < K1_RPW; j++) {
            nacc[j] = 0.f;
#pragma unroll
            for (int p = 0; p < NP; p++) acc[j][p] = 0ull;
        }

        float2 xv01[K1_RPW], xv23[K1_RPW];
#pragma unroll
        for (int j = 0; j < K1_RPW; j++) {
            xv01[j] = __ldcs((const float2*)(X + ro[j]));
            xv23[j] = __ldcs((const float2*)(X + ro[j] + 64));
        }

#pragma unroll
        for (int kk = 0; kk < 8; kk++) {
            u64 xd[K1_RPW][4];
#pragma unroll
            for (int j = 0; j < K1_RPW; j++) {
                xd[j][0] = fdup(xv01[j].x); xd[j][1] = fdup(xv01[j].y);
                xd[j][2] = fdup(xv23[j].x); xd[j][3] = fdup(xv23[j].y);
                nacc[j] = fmaf(xv01[j].x, xv01[j].x, nacc[j]);
                nacc[j] = fmaf(xv01[j].y, xv01[j].y, nacc[j]);
                nacc[j] = fmaf(xv23[j].x, xv23[j].x, nacc[j]);
                nacc[j] = fmaf(xv23[j].y, xv23[j].y, nacc[j]);
            }
            if (kk < 7) {
                int nb = (kk + 1) * 128;
#pragma unroll
                for (int j = 0; j < K1_RPW; j++) {
                    xv01[j] = __ldcs((const float2*)(X + ro[j] + nb));
                    xv23[j] = __ldcs((const float2*)(X + ro[j] + nb + 64));
                }
            }
            int cb = kk * 128 + 2 * lane;
#pragma unroll
            for (int p = 0; p < NP; p++) {
                ulonglong2 qa = *(const ulonglong2*)&s_qp[p * C_DIM + cb];
                ulonglong2 qb = *(const ulonglong2*)&s_qp[p * C_DIM + cb + 64];
#pragma unroll
                for (int j = 0; j < K1_RPW; j++) {
                    acc[j][p] = f2fma(xd[j][0], qa.x, acc[j][p]);
                    acc[j][p] = f2fma(xd[j][1], qa.y, acc[j][p]);
                    acc[j][p] = f2fma(xd[j][2], qb.x, acc[j][p]);
                    acc[j][p] = f2fma(xd[j][3], qb.y, acc[j][p]);
                }
            }
        }

        // packed lane reduction + scale + stage
#pragma unroll
        for (int j = 0; j < K1_RPW; j++) {
            float ns = nacc[j];
#pragma unroll
            for (int off = 16; off; off >>= 1) {
                ns += __shfl_xor_sync(0xffffffffu, ns, off);
#pragma unroll
                for (int p = 0; p < NP; p++)
                    acc[j][p] = f2add(acc[j][p], shfl_xor64(acc[j][p], off));
            }
            if (lane == 0) {
                int slot = warp * K1_RPW + j;
                if (row0 + j < N) {
                    float sc = 100.0f / fmaxf(sqrtf(ns), 1e-12f);
#pragma unroll
                    for (int p = 0; p < NP; p++) {
                        float l0 = f2lo(acc[j][p]) * sc;
                        float l1 = f2hi(acc[j][p]) * sc;
                        s_l[2 * p][slot] = l0;
                        s_l[2 * p + 1][slot] = l1;
                        s_wmax[warp][2 * p] = fmaxf(s_wmax[warp][2 * p], l0);
                        s_wmax[warp][2 * p + 1] = fmaxf(s_wmax[warp][2 * p + 1], l1);
                    }
                } else {
#pragma unroll
                    for (int q = 0; q < NQ; q++) s_l[q][slot] = -1e30f;
                }
            }
        }
        __syncthreads();

        // coalesced logit store
        int col0 = tile * K1_RPB;
        for (int i = t; i < NQ * K1_RPB; i += 256) {
            int q = i >> 5, c = i & (K1_RPB - 1);
            int n = col0 + c;
            if (n < N) g_logits[(size_t)q * N + n] = s_l[q][c];
        }
        __syncthreads();   // protect s_l before next tile overwrites
    }

    __syncthreads();
    if (t < NQ) {
        float m = -1e30f;
#pragma unroll
        for (int w = 0; w < K1_WARPS; w++) m = fmaxf(m, s_wmax[w][t]);
        g_bmax[(size_t)blockIdx.x * NQ + t] = m;
    }
}

// ============================================================
// K1m: merge per-block maxes -> g_M  (1 block, warp per q)
// ============================================================
__global__ void k1_merge(int nblocks) {
    int q = threadIdx.x >> 5, lane = threadIdx.x & 31;
    if (q >= NQ) return;
    float m = -1e30f;
    for (int b = lane; b < nblocks; b += 32)
        m = fmaxf(m, g_bmax[(size_t)b * NQ + q]);
#pragma unroll
    for (int off = 16; off; off >>= 1)
        m = fmaxf(m, __shfl_xor_sync(0xffffffffu, m, off));
    if (lane == 0) g_M[q] = m;
}

// ============================================================
// K1.5b: Z[q] = sum_n exp(l - M)   (grid = NQ*32 blocks)
// ============================================================
__global__ void k15b_z(int N) {
    int q = blockIdx.x >> 5, part = blockIdx.x & 31;
    const float* l = g_logits + (size_t)q * N;
    float M = g_M[q];
    float s = 0.f;
    int n4 = N >> 2;
    int stride = 32 * 256;
    for (int i = part * 256 + threadIdx.x; i < n4; i += stride) {
        float4 v = *(const float4*)(l + 4 * i);
        s += __expf(v.x - M) + __expf(v.y - M) + __expf(v.z - M) + __expf(v.w - M);
    }
    for (int n = 4 * n4 + part * 256 + threadIdx.x; n < N; n += stride)
        s += __expf(l[n] - M);
    __shared__ float red[256];
    int t = threadIdx.x;
    red[t] = s;
    __syncthreads();
    for (int st = 128; st > 0; st >>= 1) {
        if (t < st) red[t] += red[t + st];
        __syncthreads();
    }
    if (t == 0) atomicAdd(&g_Z[q], red[0]);
}

// ============================================================
// K2: persistent; acc[c] += g[n]*X[n][c] over block's tiles
//     g[n] = (1/NQ) * sum_q exp(l[q][n]-M_q)/Z_q
// ============================================================
__global__ __launch_bounds__(256) void k2_wsum(const float* __restrict__ X,
                                               int N, int ntiles) {
    __shared__ float s_g[K2_TILE];
    __shared__ float s_m[NQ], s_iz[NQ];
    int t = threadIdx.x;
    if (t < NQ) { s_m[t] = g_M[t]; s_iz[t] = (1.0f / NQ) / g_Z[t]; }
    __syncthreads();

    float4 a = make_float4(0.f, 0.f, 0.f, 0.f);

    for (int tile = blockIdx.x; tile < ntiles; tile += gridDim.x) {
        int n0 = tile * K2_TILE;
        int nv = min(K2_TILE, N - n0);
        __syncthreads();   // previous tile's s_g reads complete
        if (t < K2_TILE) {
            float gs = 0.f;
            if (t < nv) {
                int n = n0 + t;
#pragma unroll
                for (int q = 0; q < NQ; q++)
                    gs = fmaf(__expf(g_logits[(size_t)q * N + n] - s_m[q]), s_iz[q], gs);
            }
            s_g[t] = gs;
        }
        __syncthreads();

        const float* xb = X + (size_t)n0 * C_DIM + 4 * t;
        int r = 0;
        for (; r + 8 <= nv; r += 8) {
            float4 x[8];
#pragma unroll
            for (int i = 0; i < 8; i++)
                x[i] = __ldcs((const float4*)(xb + (size_t)(r + i) * C_DIM));
#pragma unroll
            for (int i = 0; i < 8; i++) {
                float g = s_g[r + i];
                a.x = fmaf(g, x[i].x, a.x); a.y = fmaf(g, x[i].y, a.y);
                a.z = fmaf(g, x[i].z, a.z); a.w = fmaf(g, x[i].w, a.w);
            }
        }
        for (; r < nv; r++) {
            float4 x = __ldcs((const float4*)(xb + (size_t)r * C_DIM));
            float g = s_g[r];
            a.x = fmaf(g, x.x, a.x); a.y = fmaf(g, x.y, a.y);
            a.z = fmaf(g, x.z, a.z); a.w = fmaf(g, x.w, a.w);
        }
    }
    *(float4*)(g_partial + (size_t)blockIdx.x * C_DIM + 4 * t) = a;
}

// ============================================================
// K2.5: pooled[c] = sum_b partial[b][c]   (grid 64 x 128)
// ============================================================
__global__ void k25_reduce(int nblocks) {
    int cpart = blockIdx.x & 7;
    int bpart = blockIdx.x >> 3;
    int c = cpart * 128 + threadIdx.x;
    float s = 0.f;
    for (int bb = bpart; bb < nblocks; bb += 8)
        s += g_partial[(size_t)bb * C_DIM + c];
    atomicAdd(&g_pooled[c], s);
}

// ============================================================
// K3: out[j] = b[j] + sum_c pooled[c]*W[j][c]   (grid 128 x 256)
// ============================================================
__global__ __launch_bounds__(256) void k3_linear(const float* __restrict__ W,
                                                 const float* __restrict__ bias,
                                                 float* __restrict__ out) {
    int t = threadIdx.x;
    int j0 = blockIdx.x * 8;
    float4 p = *(const float4*)(g_pooled + 4 * t);
    float part[8];
#pragma unroll
    for (int j = 0; j < 8; j++) {
        const float4 w = *(const float4*)(W + (size_t)(j0 + j) * C_DIM + 4 * t);
        part[j] = fmaf(p.x, w.x, fmaf(p.y, w.y, fmaf(p.z, w.z, p.w * w.w)));
    }
#pragma unroll
    for (int j = 0; j < 8; j++)
#pragma unroll
        for (int off = 16; off; off >>= 1)
            part[j] += __shfl_xor_sync(0xffffffffu, part[j], off);
    __shared__ float s_p[8][8];
    int warp = t >> 5, lane = t & 31;
    if (lane == 0)
#pragma unroll
        for (int j = 0; j < 8; j++) s_p[warp][j] = part[j];
    __syncthreads();
    if (t < 8) {
        float s = 0.f;
#pragma unroll
        for (int w = 0; w < 8; w++) s += s_p[w][t];
        out[j0 + t] = s + bias[j0 + t];
    }
}

// ============================================================
extern "C" void kernel_launch(void* const* d_in, const int* in_sizes, int n_in,
                              void* d_out, int out_size) {
    const float* X = (const float*)d_in[0];
    const float* Q = (const float*)d_in[1];
    const float* W = (const float*)d_in[2];
    const float* b = (const float*)d_in[3];
    float* out = (float*)d_out;

    int N = in_sizes[0] / C_DIM;
    if (N > MAXN) N = MAXN;

    int k1_tiles = (N + K1_RPB - 1) / K1_RPB;
    int k2_tiles = (N + K2_TILE - 1) / K2_TILE;
    int k1_grid = (K1_GRID < k1_tiles) ? K1_GRID : k1_tiles;
    int k2_grid = (K2_GRID < k2_tiles) ? K2_GRID : k2_tiles;

    k0_prep<<<1, 128>>>(Q);
    k1_logits<<<k1_grid, 256>>>(X, N, k1_tiles);
    k1_merge<<<1, NQ * 32>>>(k1_grid);
    k15b_z<<<NQ * 32, 256>>>(N);
    k2_wsum<<<k2_grid, 256>>>(X, N, k2_tiles);
    k25_reduce<<<64, 128>>>(k2_grid);
    k3_linear<<<128, 256>>>(W, b, out);
}

// round 6
// speedup vs baseline: 1.0869x; 1.0869x over previous
#include <cuda_runtime.h>
#include <math.h>

#define C_DIM 1024
#define NQ 10            // gated queries (ref has NQ+1 = 11 query rows)
#define MAXN 100000
#define K1_RPW 2         // rows per warp per tile
#define K1_WARPS 8
#define K1_RPB (K1_RPW * K1_WARPS)   // 16 rows per tile
#define K1_GRID 296                  // persistent, 2 CTAs/SM (16 warps)
#define K2_TILE 128
#define K2_GRID 592                  // persistent, 4 CTAs/SM

typedef unsigned long long u64;

// ---- scratch (static device memory; no allocations) ----
__device__ float g_Qd[NQ * C_DIM];                    // Qn[q] - Qn[NQ], q-major
__device__ float g_logits[(size_t)NQ * MAXN];         // [q][n], 4 MB
__device__ float g_bmax[(size_t)K1_GRID * NQ];        // per-block max partials
__device__ float g_M[NQ];                             // per-q max logit
__device__ float g_Z[NQ];                             // per-q softmax denom
__device__ float g_partial[(size_t)K2_GRID * C_DIM];  // pass-2 partials
__device__ float g_pooled[C_DIM];

// ---- packed f32x2 helpers ----
__device__ __forceinline__ u64 f2fma(u64 a, u64 b, u64 c) {
    u64 d;
    asm("fma.rn.f32x2 %0, %1, %2, %3;" : "=l"(d) : "l"(a), "l"(b), "l"(c));
    return d;
}
__device__ __forceinline__ float f2sum(u64 v) {
    return __uint_as_float((unsigned)v) + __uint_as_float((unsigned)(v >> 32));
}

// ============================================================
// K0: normalize Q rows, build Qd = Qn[q]-Qn[NQ]; init Z/pooled
// ============================================================
__global__ void k0_prep(const float* __restrict__ Q) {
    __shared__ float s_inv[NQ + 1];
    __shared__ float s_red[128];
    int t = threadIdx.x;
    for (int q = 0; q < NQ + 1; q++) {
        float ss = 0.f;
        for (int c = t; c < C_DIM; c += 128) {
            float v = Q[q * C_DIM + c];
            ss = fmaf(v, v, ss);
        }
        s_red[t] = ss;
        __syncthreads();
        for (int s = 64; s > 0; s >>= 1) {
            if (t < s) s_red[t] += s_red[t + s];
            __syncthreads();
        }
        if (t == 0) s_inv[q] = 1.0f / fmaxf(sqrtf(s_red[0]), 1e-12f);
        __syncthreads();
    }
    float invL = s_inv[NQ];
    for (int c = t; c < C_DIM; c += 128) {
        float ql = Q[NQ * C_DIM + c] * invL;
        for (int q = 0; q < NQ; q++)
            g_Qd[q * C_DIM + c] = Q[q * C_DIM + c] * s_inv[q] - ql;
    }
    if (t < NQ) g_Z[t] = 0.f;
    for (int c = t; c < C_DIM; c += 128) g_pooled[c] = 0.f;
}

// ============================================================
// K1: logits[q][n] = 100 * (Qd[q] . X[n]) / max(||X[n]||, eps)
// persistent, 2 CTAs/SM (16 warps), warp = 2 rows/tile,
// triple-buffered X prefetch (2 chunks ahead), packed f32x2 FMA
// ============================================================
__global__ __launch_bounds__(256, 2) void k1_logits(const float* __restrict__ X,
                                                    int N, int ntiles) {
    __shared__ float s_qd[NQ * C_DIM];          // 40 KB
    __shared__ float s_l[NQ][K1_RPB];
    __shared__ float s_wmax[K1_WARPS][NQ];
    int t = threadIdx.x;
    int warp = t >> 5, lane = t & 31;
    for (int i = t; i < NQ * C_DIM; i += 256) s_qd[i] = g_Qd[i];
    if (t < K1_WARPS * NQ) ((float*)s_wmax)[t] = -1e30f;
    __syncthreads();

    for (int tile = blockIdx.x; tile < ntiles; tile += gridDim.x) {
        int row0 = tile * K1_RPB + warp * K1_RPW;

        const float* xp[K1_RPW];
#pragma unroll
        for (int j = 0; j < K1_RPW; j++) {
            int r = row0 + j;
            if (r > N - 1) r = N - 1;
            xp[j] = X + (size_t)r * C_DIM + lane * 4;
        }

        u64 acc[K1_RPW][NQ];
        u64 nacc[K1_RPW];
#pragma unroll
        for (int j = 0; j < K1_RPW; j++) {
            nacc[j] = 0ull;
#pragma unroll
            for (int q = 0; q < NQ; q++) acc[j][q] = 0ull;
        }

        // triple buffer: preload chunks 0 and 1
        ulonglong2 xbuf[3][K1_RPW];
#pragma unroll
        for (int j = 0; j < K1_RPW; j++) {
            xbuf[0][j] = __ldcs((const ulonglong2*)(xp[j]));
            xbuf[1][j] = __ldcs((const ulonglong2*)(xp[j] + 128));
        }

#pragma unroll
        for (int kk = 0; kk < 8; kk++) {
            if (kk < 6) {
                int nb = (kk + 2) * 128;
#pragma unroll
                for (int j = 0; j < K1_RPW; j++)
                    xbuf[(kk + 2) % 3][j] = __ldcs((const ulonglong2*)(xp[j] + nb));
            }
            int cb = kk * 128 + lane * 4;
#pragma unroll
            for (int j = 0; j < K1_RPW; j++) {
                ulonglong2 x = xbuf[kk % 3][j];
                nacc[j] = f2fma(x.x, x.x, nacc[j]);
                nacc[j] = f2fma(x.y, x.y, nacc[j]);
#pragma unroll
                for (int q = 0; q < NQ; q++) {
                    ulonglong2 qv = *(const ulonglong2*)&s_qd[q * C_DIM + cb];
                    acc[j][q] = f2fma(x.x, qv.x, acc[j][q]);
                    acc[j][q] = f2fma(x.y, qv.y, acc[j][q]);
                }
            }
        }

        // lane reduction + scale + stage
#pragma unroll
        for (int j = 0; j < K1_RPW; j++) {
            float ns = f2sum(nacc[j]);
            float dot[NQ];
#pragma unroll
            for (int q = 0; q < NQ; q++) dot[q] = f2sum(acc[j][q]);
#pragma unroll
            for (int off = 16; off; off >>= 1) {
                ns += __shfl_xor_sync(0xffffffffu, ns, off);
#pragma unroll
                for (int q = 0; q < NQ; q++)
                    dot[q] += __shfl_xor_sync(0xffffffffu, dot[q], off);
            }
            if (lane == 0) {
                int slot = warp * K1_RPW + j;
                if (row0 + j < N) {
                    float sc = 100.0f / fmaxf(sqrtf(ns), 1e-12f);
#pragma unroll
                    for (int q = 0; q < NQ; q++) {
                        float lv = dot[q] * sc;
                        s_l[q][slot] = lv;
                        s_wmax[warp][q] = fmaxf(s_wmax[warp][q], lv);
                    }
                } else {
#pragma unroll
                    for (int q = 0; q < NQ; q++) s_l[q][slot] = -1e30f;
                }
            }
        }
        __syncthreads();

        // coalesced logit store (NQ*16 = 160 values)
        int col0 = tile * K1_RPB;
        if (t < NQ * K1_RPB) {
            int q = t >> 4, c = t & (K1_RPB - 1);
            int n = col0 + c;
            if (n < N) g_logits[(size_t)q * N + n] = s_l[q][c];
        }
        __syncthreads();   // protect s_l before next tile overwrites
    }

    __syncthreads();
    if (t < NQ) {
        float m = -1e30f;
#pragma unroll
        for (int w = 0; w < K1_WARPS; w++) m = fmaxf(m, s_wmax[w][t]);
        g_bmax[(size_t)blockIdx.x * NQ + t] = m;
    }
}

// ============================================================
// K1.5b: Z[q] = sum_n exp(l - M); M computed from g_bmax in-kernel
// (grid = NQ*32 blocks; part 0 publishes g_M[q])
// ============================================================
__global__ void k15b_z(int N, int nbmax) {
    int q = blockIdx.x >> 5, part = blockIdx.x & 31;
    int t = threadIdx.x;
    __shared__ float red[256];

    // local merge of per-block maxes
    float m = -1e30f;
    for (int b = t; b < nbmax; b += 256)
        m = fmaxf(m, g_bmax[(size_t)b * NQ + q]);
    red[t] = m;
    __syncthreads();
    for (int s = 128; s > 0; s >>= 1) {
        if (t < s) red[t] = fmaxf(red[t], red[t + s]);
        __syncthreads();
    }
    float M = red[0];
    if (part == 0 && t == 0) g_M[q] = M;
    __syncthreads();

    const float* l = g_logits + (size_t)q * N;
    float s = 0.f;
    int n4 = N >> 2;
    int stride = 32 * 256;
    for (int i = part * 256 + t; i < n4; i += stride) {
        float4 v = *(const float4*)(l + 4 * i);
        s += __expf(v.x - M) + __expf(v.y - M) + __expf(v.z - M) + __expf(v.w - M);
    }
    for (int n = 4 * n4 + part * 256 + t; n < N; n += stride)
        s += __expf(l[n] - M);
    red[t] = s;
    __syncthreads();
    for (int st = 128; st > 0; st >>= 1) {
        if (t < st) red[t] += red[t + st];
        __syncthreads();
    }
    if (t == 0) atomicAdd(&g_Z[q], red[0]);
}

// ============================================================
// K2: persistent; acc[c] += g[n]*X[n][c] over block's tiles
//     g[n] = (1/NQ) * sum_q exp(l[q][n]-M_q)/Z_q
// ============================================================
__global__ __launch_bounds__(256) void k2_wsum(const float* __restrict__ X,
                                               int N, int ntiles) {
    __shared__ float s_g[K2_TILE];
    __shared__ float s_m[NQ], s_iz[NQ];
    int t = threadIdx.x;
    if (t < NQ) { s_m[t] = g_M[t]; s_iz[t] = (1.0f / NQ) / g_Z[t]; }
    __syncthreads();

    float4 a = make_float4(0.f, 0.f, 0.f, 0.f);

    for (int tile = blockIdx.x; tile < ntiles; tile += gridDim.x) {
        int n0 = tile * K2_TILE;
        int nv = min(K2_TILE, N - n0);
        __syncthreads();   // previous tile's s_g reads complete
        if (t < K2_TILE) {
            float gs = 0.f;
            if (t < nv) {
                int n = n0 + t;
#pragma unroll
                for (int q = 0; q < NQ; q++)
                    gs = fmaf(__expf(g_logits[(size_t)q * N + n] - s_m[q]), s_iz[q], gs);
            }
            s_g[t] = gs;
        }
        __syncthreads();

        const float* xb = X + (size_t)n0 * C_DIM + 4 * t;
        int r = 0;
        for (; r + 8 <= nv; r += 8) {
            float4 x[8];
#pragma unroll
            for (int i = 0; i < 8; i++)
                x[i] = __ldcs((const float4*)(xb + (size_t)(r + i) * C_DIM));
#pragma unroll
            for (int i = 0; i < 8; i++) {
                float g = s_g[r + i];
                a.x = fmaf(g, x[i].x, a.x); a.y = fmaf(g, x[i].y, a.y);
                a.z = fmaf(g, x[i].z, a.z); a.w = fmaf(g, x[i].w, a.w);
            }
        }
        for (; r < nv; r++) {
            float4 x = __ldcs((const float4*)(xb + (size_t)r * C_DIM));
            float g = s_g[r];
            a.x = fmaf(g, x.x, a.x); a.y = fmaf(g, x.y, a.y);
            a.z = fmaf(g, x.z, a.z); a.w = fmaf(g, x.w, a.w);
        }
    }
    *(float4*)(g_partial + (size_t)blockIdx.x * C_DIM + 4 * t) = a;
}

// ============================================================
// K2.5: pooled[c] = sum_b partial[b][c]   (grid 64 x 128)
// ============================================================
__global__ void k25_reduce(int nblocks) {
    int cpart = blockIdx.x & 7;
    int bpart = blockIdx.x >> 3;
    int c = cpart * 128 + threadIdx.x;
    float s = 0.f;
    for (int bb = bpart; bb < nblocks; bb += 8)
        s += g_partial[(size_t)bb * C_DIM + c];
    atomicAdd(&g_pooled[c], s);
}

// ============================================================
// K3: out[j] = b[j] + sum_c pooled[c]*W[j][c]   (grid 128 x 256)
// ============================================================
__global__ __launch_bounds__(256) void k3_linear(const float* __restrict__ W,
                                                 const float* __restrict__ bias,
                                                 float* __restrict__ out) {
    int t = threadIdx.x;
    int j0 = blockIdx.x * 8;
    float4 p = *(const float4*)(g_pooled + 4 * t);
    float part[8];
#pragma unroll
    for (int j = 0; j < 8; j++) {
        const float4 w = *(const float4*)(W + (size_t)(j0 + j) * C_DIM + 4 * t);
        part[j] = fmaf(p.x, w.x, fmaf(p.y, w.y, fmaf(p.z, w.z, p.w * w.w)));
    }
#pragma unroll
    for (int j = 0; j < 8; j++)
#pragma unroll
        for (int off = 16; off; off >>= 1)
            part[j] += __shfl_xor_sync(0xffffffffu, part[j], off);
    __shared__ float s_p[8][8];
    int warp = t >> 5, lane = t & 31;
    if (lane == 0)
#pragma unroll
        for (int j = 0; j < 8; j++) s_p[warp][j] = part[j];
    __syncthreads();
    if (t < 8) {
        float s = 0.f;
#pragma unroll
        for (int w = 0; w < 8; w++) s += s_p[w][t];
        out[j0 + t] = s + bias[j0 + t];
    }
}

// ============================================================
extern "C" void kernel_launch(void* const* d_in, const int* in_sizes, int n_in,
                              void* d_out, int out_size) {
    const float* X = (const float*)d_in[0];
    const float* Q = (const float*)d_in[1];
    const float* W = (const float*)d_in[2];
    const float* b = (const float*)d_in[3];
    float* out = (float*)d_out;

    int N = in_sizes[0] / C_DIM;
    if (N > MAXN) N = MAXN;

    int k1_tiles = (N + K1_RPB - 1) / K1_RPB;
    int k2_tiles = (N + K2_TILE - 1) / K2_TILE;
    int k1_grid = (K1_GRID < k1_tiles) ? K1_GRID : k1_tiles;
    int k2_grid = (K2_GRID < k2_tiles) ? K2_GRID : k2_tiles;

    k0_prep<<<1, 128>>>(Q);
    k1_logits<<<k1_grid, 256>>>(X, N, k1_tiles);
    k15b_z<<<NQ * 32, 256>>>(N, k1_grid);
    k2_wsum<<<k2_grid, 256>>>(X, N, k2_tiles);
    k25_reduce<<<64, 128>>>(k2_grid);
    k3_linear<<<128, 256>>>(W, b, out);
}

// round 7
// speedup vs baseline: 1.1240x; 1.0342x over previous
#include <cuda_runtime.h>
#include <math.h>

#define C_DIM 1024
#define NQ 10            // gated queries (ref has NQ+1 = 11 query rows)
#define NP 5             // q-pairs
#define MAXN 100000
#define K1_RPW 4         // rows per warp per tile
#define K1_WARPS 8
#define K1_RPB (K1_RPW * K1_WARPS)   // 32 rows per tile
#define K1_GRID 296                  // persistent, 2 CTAs/SM (16 warps)
#define K2_TILE 128
#define K2_GRID 592                  // persistent, 4 CTAs/SM

typedef unsigned long long u64;

// ---- scratch (static device memory; no allocations) ----
__device__ u64   g_Qp[NP * C_DIM];                    // packed q-pair diffs [p][c]
__device__ float g_logits[(size_t)NQ * MAXN];         // [q][n], 4 MB
__device__ float g_bmax[(size_t)K1_GRID * NQ];        // per-block max partials
__device__ float g_M[NQ];                             // per-q max logit
__device__ float g_Z[NQ];                             // per-q softmax denom
__device__ float g_partial[(size_t)K2_GRID * C_DIM];  // pass-2 partials
__device__ float g_pooled[C_DIM];

// ---- packed f32x2 helpers ----
__device__ __forceinline__ u64 f2fma(u64 a, u64 b, u64 c) {
    u64 d;
    asm("fma.rn.f32x2 %0, %1, %2, %3;" : "=l"(d) : "l"(a), "l"(b), "l"(c));
    return d;
}
__device__ __forceinline__ u64 f2add(u64 a, u64 b) {
    u64 d;
    asm("add.rn.f32x2 %0, %1, %2;" : "=l"(d) : "l"(a), "l"(b));
    return d;
}
__device__ __forceinline__ u64 fdup(float x) {
    u64 d;
    asm("mov.b64 %0, {%1, %1};" : "=l"(d) : "f"(x));
    return d;
}
__device__ __forceinline__ u64 fpack(float lo, float hi) {
    u64 d;
    asm("mov.b64 %0, {%1, %2};" : "=l"(d) : "f"(lo), "f"(hi));
    return d;
}
__device__ __forceinline__ float f2lo(u64 v) { return __uint_as_float((unsigned)v); }
__device__ __forceinline__ float f2hi(u64 v) { return __uint_as_float((unsigned)(v >> 32)); }
__device__ __forceinline__ float f2sum(u64 v) { return f2lo(v) + f2hi(v); }
__device__ __forceinline__ u64 shfl_xor64(u64 v, int off) {
    unsigned lo = (unsigned)v, hi = (unsigned)(v >> 32);
    lo = __shfl_xor_sync(0xffffffffu, lo, off);
    hi = __shfl_xor_sync(0xffffffffu, hi, off);
    return (u64)lo | ((u64)hi << 32);
}

// ============================================================
// K0: normalize Q rows, build packed Qp pairs; init Z/pooled
// ============================================================
__global__ void k0_prep(const float* __restrict__ Q) {
    __shared__ float s_inv[NQ + 1];
    __shared__ float s_red[128];
    int t = threadIdx.x;
    for (int q = 0; q < NQ + 1; q++) {
        float ss = 0.f;
        for (int c = t; c < C_DIM; c += 128) {
            float v = Q[q * C_DIM + c];
            ss = fmaf(v, v, ss);
        }
        s_red[t] = ss;
        __syncthreads();
        for (int s = 64; s > 0; s >>= 1) {
            if (t < s) s_red[t] += s_red[t + s];
            __syncthreads();
        }
        if (t == 0) s_inv[q] = 1.0f / fmaxf(sqrtf(s_red[0]), 1e-12f);
        __syncthreads();
    }
    float invL = s_inv[NQ];
    for (int c = t; c < C_DIM; c += 128) {
        float ql = Q[NQ * C_DIM + c] * invL;
#pragma unroll
        for (int p = 0; p < NP; p++) {
            float lo = Q[(2 * p) * C_DIM + c] * s_inv[2 * p] - ql;
            float hi = Q[(2 * p + 1) * C_DIM + c] * s_inv[2 * p + 1] - ql;
            g_Qp[p * C_DIM + c] = fpack(lo, hi);
        }
    }
    if (t < NQ) g_Z[t] = 0.f;
    for (int c = t; c < C_DIM; c += 128) g_pooled[c] = 0.f;
}

// ============================================================
// K1: logits[q][n] = 100 * (Qd[q] . X[n]) / max(||X[n]||, eps)
// RPW=4, q-pair packed acc (40 regs), 2 CTAs/SM, no spills.
// Lane owns cols {2l,2l+1} and {64+2l,64+2l+1} per 128-chunk
// (conflict-free LDS.128 for Q pairs and 8B-coalesced X loads).
// ============================================================
__global__ __launch_bounds__(256, 2) void k1_logits(const float* __restrict__ X,
                                                    int N, int ntiles) {
    __shared__ u64 s_qp[NP * C_DIM];            // 40 KB
    __shared__ float s_l[NQ][K1_RPB];
    __shared__ float s_wmax[K1_WARPS][NQ];
    int t = threadIdx.x;
    int warp = t >> 5, lane = t & 31;
    for (int i = t; i < NP * C_DIM; i += 256) s_qp[i] = g_Qp[i];
    if (t < K1_WARPS * NQ) ((float*)s_wmax)[t] = -1e30f;
    __syncthreads();

    for (int tile = blockIdx.x; tile < ntiles; tile += gridDim.x) {
        int row0 = tile * K1_RPB + warp * K1_RPW;
        int ro[K1_RPW];
#pragma unroll
        for (int j = 0; j < K1_RPW; j++) {
            int r = row0 + j;
            if (r > N - 1) r = N - 1;
            ro[j] = r * C_DIM + 2 * lane;
        }

        u64 acc[K1_RPW][NP];
        u64 nacc[K1_RPW];
#pragma unroll
        for (int j = 0; j < K1_RPW; j++) {
            nacc[j] = 0ull;
#pragma unroll
            for (int p = 0; p < NP; p++) acc[j][p] = 0ull;
        }

        // prefetch buffer: next chunk's X (cols 2l,2l+1 and 64+2l,64+2l+1)
        u64 nx0[K1_RPW], nx1[K1_RPW];
#pragma unroll
        for (int j = 0; j < K1_RPW; j++) {
            nx0[j] = __ldcs((const u64*)(X + ro[j]));
            nx1[j] = __ldcs((const u64*)(X + ro[j] + 64));
        }

#pragma unroll
        for (int kk = 0; kk < 8; kk++) {
            // consume prefetch into dup registers + norm acc
            u64 xd[K1_RPW][4];
#pragma unroll
            for (int j = 0; j < K1_RPW; j++) {
                u64 x0 = nx0[j], x1 = nx1[j];
                xd[j][0] = fdup(f2lo(x0)); xd[j][1] = fdup(f2hi(x0));
                xd[j][2] = fdup(f2lo(x1)); xd[j][3] = fdup(f2hi(x1));
                nacc[j] = f2fma(x0, x0, nacc[j]);
                nacc[j] = f2fma(x1, x1, nacc[j]);
            }
            // issue next chunk's loads
            if (kk < 7) {
                int nb = (kk + 1) * 128;
#pragma unroll
                for (int j = 0; j < K1_RPW; j++) {
                    nx0[j] = __ldcs((const u64*)(X + ro[j] + nb));
                    nx1[j] = __ldcs((const u64*)(X + ro[j] + nb + 64));
                }
            }
            // compute current chunk against 5 q-pairs
            int cb = kk * 128 + 2 * lane;
#pragma unroll
            for (int p = 0; p < NP; p++) {
                ulonglong2 qa = *(const ulonglong2*)&s_qp[p * C_DIM + cb];
                ulonglong2 qb = *(const ulonglong2*)&s_qp[p * C_DIM + cb + 64];
#pragma unroll
                for (int j = 0; j < K1_RPW; j++) {
                    acc[j][p] = f2fma(xd[j][0], qa.x, acc[j][p]);
                    acc[j][p] = f2fma(xd[j][1], qa.y, acc[j][p]);
                    acc[j][p] = f2fma(xd[j][2], qb.x, acc[j][p]);
                    acc[j][p] = f2fma(xd[j][3], qb.y, acc[j][p]);
                }
            }
        }

        // packed lane reduction + scale + stage
#pragma unroll
        for (int j = 0; j < K1_RPW; j++) {
#pragma unroll
            for (int off = 16; off; off >>= 1) {
                nacc[j] = f2add(nacc[j], shfl_xor64(nacc[j], off));
#pragma unroll
                for (int p = 0; p < NP; p++)
                    acc[j][p] = f2add(acc[j][p], shfl_xor64(acc[j][p], off));
            }
            if (lane == 0) {
                int slot = warp * K1_RPW + j;
                if (row0 + j < N) {
                    float ns = f2sum(nacc[j]);
                    float sc = 100.0f / fmaxf(sqrtf(ns), 1e-12f);
#pragma unroll
                    for (int p = 0; p < NP; p++) {
                        float l0 = f2lo(acc[j][p]) * sc;
                        float l1 = f2hi(acc[j][p]) * sc;
                        s_l[2 * p][slot] = l0;
                        s_l[2 * p + 1][slot] = l1;
                        s_wmax[warp][2 * p] = fmaxf(s_wmax[warp][2 * p], l0);
                        s_wmax[warp][2 * p + 1] = fmaxf(s_wmax[warp][2 * p + 1], l1);
                    }
                } else {
#pragma unroll
                    for (int q = 0; q < NQ; q++) s_l[q][slot] = -1e30f;
                }
            }
        }
        __syncthreads();

        // coalesced logit store (NQ*32 = 320 values)
        int col0 = tile * K1_RPB;
        for (int i = t; i < NQ * K1_RPB; i += 256) {
            int q = i >> 5, c = i & (K1_RPB - 1);
            int n = col0 + c;
            if (n < N) g_logits[(size_t)q * N + n] = s_l[q][c];
        }
        __syncthreads();   // protect s_l before next tile overwrites
    }

    __syncthreads();
    if (t < NQ) {
        float m = -1e30f;
#pragma unroll
        for (int w = 0; w < K1_WARPS; w++) m = fmaxf(m, s_wmax[w][t]);
        g_bmax[(size_t)blockIdx.x * NQ + t] = m;
    }
}

// ============================================================
// K1.5b: Z[q] = sum_n exp(l - M); M merged from g_bmax in-kernel
// (grid = NQ*32 blocks; part 0 publishes g_M[q])
// ============================================================
__global__ void k15b_z(int N, int nbmax) {
    int q = blockIdx.x >> 5, part = blockIdx.x & 31;
    int t = threadIdx.x;
    __shared__ float red[256];

    float m = -1e30f;
    for (int b = t; b < nbmax; b += 256)
        m = fmaxf(m, g_bmax[(size_t)b * NQ + q]);
    red[t] = m;
    __syncthreads();
    for (int s = 128; s > 0; s >>= 1) {
        if (t < s) red[t] = fmaxf(red[t], red[t + s]);
        __syncthreads();
    }
    float M = red[0];
    if (part == 0 && t == 0) g_M[q] = M;
    __syncthreads();

    const float* l = g_logits + (size_t)q * N;
    float s = 0.f;
    int n4 = N >> 2;
    int stride = 32 * 256;
    for (int i = part * 256 + t; i < n4; i += stride) {
        float4 v = *(const float4*)(l + 4 * i);
        s += __expf(v.x - M) + __expf(v.y - M) + __expf(v.z - M) + __expf(v.w - M);
    }
    for (int n = 4 * n4 + part * 256 + t; n < N; n += stride)
        s += __expf(l[n] - M);
    red[t] = s;
    __syncthreads();
    for (int st = 128; st > 0; st >>= 1) {
        if (t < st) red[t] += red[t + st];
        __syncthreads();
    }
    if (t == 0) atomicAdd(&g_Z[q], red[0]);
}

// ============================================================
// K2: persistent; acc[c] += g[n]*X[n][c] over block's tiles
//     g[n] = (1/NQ) * sum_q exp(l[q][n]-M_q)/Z_q
// softmax gather split across both half-blocks (5 q's each)
// ============================================================
__global__ __launch_bounds__(256) void k2_wsum(const float* __restrict__ X,
                                               int N, int ntiles) {
    __shared__ float s_gp[2][K2_TILE];
    __shared__ float s_m[NQ], s_iz[NQ];
    int t = threadIdx.x;
    if (t < NQ) { s_m[t] = g_M[t]; s_iz[t] = (1.0f / NQ) / g_Z[t]; }
    __syncthreads();

    int half = t >> 7;          // 0 or 1
    int hr = t & 127;           // row within tile for gather
    float4 a = make_float4(0.f, 0.f, 0.f, 0.f);

    for (int tile = blockIdx.x; tile < ntiles; tile += gridDim.x) {
        int n0 = tile * K2_TILE;
        int nv = min(K2_TILE, N - n0);
        __syncthreads();   // previous tile's s_gp reads complete
        {
            float gs = 0.f;
            if (hr < nv) {
                int n = n0 + hr;
                int q0 = half * 5;
#pragma unroll
                for (int qq = 0; qq < 5; qq++) {
                    int q = q0 + qq;
                    gs = fmaf(__expf(g_logits[(size_t)q * N + n] - s_m[q]), s_iz[q], gs);
                }
            }
            s_gp[half][hr] = gs;
        }
        __syncthreads();

        const float* xb = X + (size_t)n0 * C_DIM + 4 * t;
        int r = 0;
        for (; r + 8 <= nv; r += 8) {
            float4 x[8];
#pragma unroll
            for (int i = 0; i < 8; i++)
                x[i] = __ldcs((const float4*)(xb + (size_t)(r + i) * C_DIM));
#pragma unroll
            for (int i = 0; i < 8; i++) {
                float g = s_gp[0][r + i] + s_gp[1][r + i];
                a.x = fmaf(g, x[i].x, a.x); a.y = fmaf(g, x[i].y, a.y);
                a.z = fmaf(g, x[i].z, a.z); a.w = fmaf(g, x[i].w, a.w);
            }
        }
        for (; r < nv; r++) {
            float4 x = __ldcs((const float4*)(xb + (size_t)r * C_DIM));
            float g = s_gp[0][r] + s_gp[1][r];
            a.x = fmaf(g, x.x, a.x); a.y = fmaf(g, x.y, a.y);
            a.z = fmaf(g, x.z, a.z); a.w = fmaf(g, x.w, a.w);
        }
    }
    *(float4*)(g_partial + (size_t)blockIdx.x * C_DIM + 4 * t) = a;
}

// ============================================================
// K2.5: pooled[c] = sum_b partial[b][c]   (grid 64 x 128)
// ============================================================
__global__ void k25_reduce(int nblocks) {
    int cpart = blockIdx.x & 7;
    int bpart = blockIdx.x >> 3;
    int c = cpart * 128 + threadIdx.x;
    float s = 0.f;
    for (int bb = bpart; bb < nblocks; bb += 8)
        s += g_partial[(size_t)bb * C_DIM + c];
    atomicAdd(&g_pooled[c], s);
}

// ============================================================
// K3: out[j] = b[j] + sum_c pooled[c]*W[j][c]   (grid 128 x 256)
// ============================================================
__global__ __launch_bounds__(256) void k3_linear(const float* __restrict__ W,
                                                 const float* __restrict__ bias,
                                                 float* __restrict__ out) {
    int t = threadIdx.x;
    int j0 = blockIdx.x * 8;
    float4 p = *(const float4*)(g_pooled + 4 * t);
    float part[8];
#pragma unroll
    for (int j = 0; j < 8; j++) {
        const float4 w = *(const float4*)(W + (size_t)(j0 + j) * C_DIM + 4 * t);
        part[j] = fmaf(p.x, w.x, fmaf(p.y, w.y, fmaf(p.z, w.z, p.w * w.w)));
    }
#pragma unroll
    for (int j = 0; j < 8; j++)
#pragma unroll
        for (int off = 16; off; off >>= 1)
            part[j] += __shfl_xor_sync(0xffffffffu, part[j], off);
    __shared__ float s_p[8][8];
    int warp = t >> 5, lane = t & 31;
    if (lane == 0)
#pragma unroll
        for (int j = 0; j < 8; j++) s_p[warp][j] = part[j];
    __syncthreads();
    if (t < 8) {
        float s = 0.f;
#pragma unroll
        for (int w = 0; w < 8; w++) s += s_p[w][t];
        out[j0 + t] = s + bias[j0 + t];
    }
}

// ============================================================
extern "C" void kernel_launch(void* const* d_in, const int* in_sizes, int n_in,
                              void* d_out, int out_size) {
    const float* X = (const float*)d_in[0];
    const float* Q = (const float*)d_in[1];
    const float* W = (const float*)d_in[2];
    const float* b = (const float*)d_in[3];
    float* out = (float*)d_out;

    int N = in_sizes[0] / C_DIM;
    if (N > MAXN) N = MAXN;

    int k1_tiles = (N + K1_RPB - 1) / K1_RPB;
    int k2_tiles = (N + K2_TILE - 1) / K2_TILE;
    int k1_grid = (K1_GRID < k1_tiles) ? K1_GRID : k1_tiles;
    int k2_grid = (K2_GRID < k2_tiles) ? K2_GRID : k2_tiles;

    k0_prep<<<1, 128>>>(Q);
    k1_logits<<<k1_grid, 256>>>(X, N, k1_tiles);
    k15b_z<<<NQ * 32, 256>>>(N, k1_grid);
    k2_wsum<<<k2_grid, 256>>>(X, N, k2_tiles);
    k25_reduce<<<64, 128>>>(k2_grid);
    k3_linear<<<128, 256>>>(W, b, out);
}

// round 8
// speedup vs baseline: 1.2610x; 1.1219x over previous
#include <cuda_runtime.h>
#include <math.h>

#define C_DIM 1024
#define NQ 10            // gated queries (ref has NQ+1 = 11 query rows)
#define NP 5             // q-pairs
#define MAXN 100000
#define K1_RPW 4         // rows per warp per tile
#define K1_WARPS 8
#define K1_RPB (K1_RPW * K1_WARPS)   // 32 rows per tile
#define K1_GRID 296                  // persistent, 2 CTAs/SM (16 warps)
#define K2_TILE 128
#define K2_GRID 592                  // persistent, 4 CTAs/SM

typedef unsigned long long u64;

// ---- scratch (static device memory; no allocations) ----
__device__ u64   g_Qp[NP * C_DIM];                    // packed q-pair diffs [p][c]
__device__ float g_logits[(size_t)NQ * MAXN];         // [q][n], 4 MB
__device__ float g_bmax[(size_t)K1_GRID * NQ];        // per-block max partials
__device__ float g_M[NQ];                             // per-q max logit
__device__ float g_Z[NQ];                             // per-q softmax denom
__device__ float g_partial[(size_t)K2_GRID * C_DIM];  // pass-2 partials
__device__ float g_pooled[C_DIM];

// ---- packed f32x2 helpers ----
__device__ __forceinline__ u64 f2fma(u64 a, u64 b, u64 c) {
    u64 d;
    asm("fma.rn.f32x2 %0, %1, %2, %3;" : "=l"(d) : "l"(a), "l"(b), "l"(c));
    return d;
}
__device__ __forceinline__ u64 f2add(u64 a, u64 b) {
    u64 d;
    asm("add.rn.f32x2 %0, %1, %2;" : "=l"(d) : "l"(a), "l"(b));
    return d;
}
__device__ __forceinline__ u64 fdup(float x) {
    u64 d;
    asm("mov.b64 %0, {%1, %1};" : "=l"(d) : "f"(x));
    return d;
}
__device__ __forceinline__ u64 fpack(float lo, float hi) {
    u64 d;
    asm("mov.b64 %0, {%1, %2};" : "=l"(d) : "f"(lo), "f"(hi));
    return d;
}
__device__ __forceinline__ float f2lo(u64 v) { return __uint_as_float((unsigned)v); }
__device__ __forceinline__ float f2hi(u64 v) { return __uint_as_float((unsigned)(v >> 32)); }
__device__ __forceinline__ float f2sum(u64 v) { return f2lo(v) + f2hi(v); }
__device__ __forceinline__ u64 shfl_xor64(u64 v, int off) {
    unsigned lo = (unsigned)v, hi = (unsigned)(v >> 32);
    lo = __shfl_xor_sync(0xffffffffu, lo, off);
    hi = __shfl_xor_sync(0xffffffffu, hi, off);
    return (u64)lo | ((u64)hi << 32);
}

// ============================================================
// K0: normalize Q rows, build packed Qp pairs; init Z/pooled
// ============================================================
__global__ void k0_prep(const float* __restrict__ Q) {
    __shared__ float s_inv[NQ + 1];
    __shared__ float s_red[128];
    int t = threadIdx.x;
    for (int q = 0; q < NQ + 1; q++) {
        float ss = 0.f;
        for (int c = t; c < C_DIM; c += 128) {
            float v = Q[q * C_DIM + c];
            ss = fmaf(v, v, ss);
        }
        s_red[t] = ss;
        __syncthreads();
        for (int s = 64; s > 0; s >>= 1) {
            if (t < s) s_red[t] += s_red[t + s];
            __syncthreads();
        }
        if (t == 0) s_inv[q] = 1.0f / fmaxf(sqrtf(s_red[0]), 1e-12f);
        __syncthreads();
    }
    float invL = s_inv[NQ];
    for (int c = t; c < C_DIM; c += 128) {
        float ql = Q[NQ * C_DIM + c] * invL;
#pragma unroll
        for (int p = 0; p < NP; p++) {
            float lo = Q[(2 * p) * C_DIM + c] * s_inv[2 * p] - ql;
            float hi = Q[(2 * p + 1) * C_DIM + c] * s_inv[2 * p + 1] - ql;
            g_Qp[p * C_DIM + c] = fpack(lo, hi);
        }
    }
    if (t < NQ) g_Z[t] = 0.f;
    for (int c = t; c < C_DIM; c += 128) g_pooled[c] = 0.f;
}

// ============================================================
// K1: logits[q][n] = 100 * (Qd[q] . X[n]) / max(||X[n]||, eps)
// RPW=4, q-pair packed acc, 2 CTAs/SM, depth-2 prefetch (A/B
// chunk buffers), no per-tile syncs, lane-0 direct STG.128.
// ============================================================
__global__ __launch_bounds__(256, 2) void k1_logits(const float* __restrict__ X,
                                                    int N, int ntiles) {
    __shared__ u64 s_qp[NP * C_DIM];            // 40 KB
    __shared__ float s_wmax[K1_WARPS][NQ];
    int t = threadIdx.x;
    int warp = t >> 5, lane = t & 31;
    for (int i = t; i < NP * C_DIM; i += 256) s_qp[i] = g_Qp[i];
    if (t < K1_WARPS * NQ) ((float*)s_wmax)[t] = -1e30f;
    __syncthreads();

    bool vec_ok = ((N & 3) == 0);

    for (int tile = blockIdx.x; tile < ntiles; tile += gridDim.x) {
        int row0 = tile * K1_RPB + warp * K1_RPW;
        int ro[K1_RPW];
#pragma unroll
        for (int j = 0; j < K1_RPW; j++) {
            int r = row0 + j;
            if (r > N - 1) r = N - 1;
            ro[j] = r * C_DIM + 2 * lane;
        }

        u64 acc[K1_RPW][NP];
        u64 nacc[K1_RPW];
#pragma unroll
        for (int j = 0; j < K1_RPW; j++) {
            nacc[j] = 0ull;
#pragma unroll
            for (int p = 0; p < NP; p++) acc[j][p] = 0ull;
        }

        // A = even chunk, B = odd chunk (depth-2 prefetch)
        u64 A0[K1_RPW], A1[K1_RPW], B0[K1_RPW], B1[K1_RPW];
#pragma unroll
        for (int j = 0; j < K1_RPW; j++) {
            A0[j] = __ldcs((const u64*)(X + ro[j]));
            A1[j] = __ldcs((const u64*)(X + ro[j] + 64));
        }
#pragma unroll
        for (int j = 0; j < K1_RPW; j++) {
            B0[j] = __ldcs((const u64*)(X + ro[j] + 128));
            B1[j] = __ldcs((const u64*)(X + ro[j] + 192));
        }

#pragma unroll
        for (int kk = 0; kk < 8; kk++) {
            u64* x0 = (kk & 1) ? B0 : A0;
            u64* x1 = (kk & 1) ? B1 : A1;
            int cb = kk * 128 + 2 * lane;
            int nb = (kk + 2) * 128;

            // ---- half 0: cols [cb, cb+1] ----
            {
                u64 xd[2 * K1_RPW];
#pragma unroll
                for (int j = 0; j < K1_RPW; j++) {
                    u64 x = x0[j];
                    xd[2 * j] = fdup(f2lo(x));
                    xd[2 * j + 1] = fdup(f2hi(x));
                    nacc[j] = f2fma(x, x, nacc[j]);
                }
                if (kk < 6) {
#pragma unroll
                    for (int j = 0; j < K1_RPW; j++)
                        x0[j] = __ldcs((const u64*)(X + ro[j] + nb));
                }
#pragma unroll
                for (int p = 0; p < NP; p++) {
                    ulonglong2 qa = *(const ulonglong2*)&s_qp[p * C_DIM + cb];
#pragma unroll
                    for (int j = 0; j < K1_RPW; j++) {
                        acc[j][p] = f2fma(xd[2 * j], qa.x, acc[j][p]);
                        acc[j][p] = f2fma(xd[2 * j + 1], qa.y, acc[j][p]);
                    }
                }
            }
            // ---- half 1: cols [cb+64, cb+65] ----
            {
                u64 xd[2 * K1_RPW];
#pragma unroll
                for (int j = 0; j < K1_RPW; j++) {
                    u64 x = x1[j];
                    xd[2 * j] = fdup(f2lo(x));
                    xd[2 * j + 1] = fdup(f2hi(x));
                    nacc[j] = f2fma(x, x, nacc[j]);
                }
                if (kk < 6) {
#pragma unroll
                    for (int j = 0; j < K1_RPW; j++)
                        x1[j] = __ldcs((const u64*)(X + ro[j] + nb + 64));
                }
#pragma unroll
                for (int p = 0; p < NP; p++) {
                    ulonglong2 qb = *(const ulonglong2*)&s_qp[p * C_DIM + cb + 64];
#pragma unroll
                    for (int j = 0; j < K1_RPW; j++) {
                        acc[j][p] = f2fma(xd[2 * j], qb.x, acc[j][p]);
                        acc[j][p] = f2fma(xd[2 * j + 1], qb.y, acc[j][p]);
                    }
                }
            }
        }

        // packed lane reduction
#pragma unroll
        for (int off = 16; off; off >>= 1) {
#pragma unroll
            for (int j = 0; j < K1_RPW; j++) {
                nacc[j] = f2add(nacc[j], shfl_xor64(nacc[j], off));
#pragma unroll
                for (int p = 0; p < NP; p++)
                    acc[j][p] = f2add(acc[j][p], shfl_xor64(acc[j][p], off));
            }
        }

        // lane 0: scale + direct vector store (4 rows per q)
        if (lane == 0) {
            float sc[K1_RPW];
#pragma unroll
            for (int j = 0; j < K1_RPW; j++) {
                float ns = f2sum(nacc[j]);
                sc[j] = 100.0f / fmaxf(sqrtf(ns), 1e-12f);
            }
            bool full = vec_ok && (row0 + K1_RPW <= N);
#pragma unroll
            for (int p = 0; p < NP; p++) {
                float4 v0, v1;
                v0.x = f2lo(acc[0][p]) * sc[0]; v1.x = f2hi(acc[0][p]) * sc[0];
                v0.y = f2lo(acc[1][p]) * sc[1]; v1.y = f2hi(acc[1][p]) * sc[1];
                v0.z = f2lo(acc[2][p]) * sc[2]; v1.z = f2hi(acc[2][p]) * sc[2];
                v0.w = f2lo(acc[3][p]) * sc[3]; v1.w = f2hi(acc[3][p]) * sc[3];
                float m0 = fmaxf(fmaxf(v0.x, v0.y), fmaxf(v0.z, v0.w));
                float m1 = fmaxf(fmaxf(v1.x, v1.y), fmaxf(v1.z, v1.w));
                if (full) {
                    *(float4*)&g_logits[(size_t)(2 * p) * N + row0] = v0;
                    *(float4*)&g_logits[(size_t)(2 * p + 1) * N + row0] = v1;
                    s_wmax[warp][2 * p] = fmaxf(s_wmax[warp][2 * p], m0);
                    s_wmax[warp][2 * p + 1] = fmaxf(s_wmax[warp][2 * p + 1], m1);
                } else {
                    const float* vv0 = &v0.x;
                    const float* vv1 = &v1.x;
                    float pm0 = -1e30f, pm1 = -1e30f;
#pragma unroll
                    for (int j = 0; j < K1_RPW; j++) {
                        if (row0 + j < N) {
                            g_logits[(size_t)(2 * p) * N + row0 + j] = vv0[j];
                            g_logits[(size_t)(2 * p + 1) * N + row0 + j] = vv1[j];
                            pm0 = fmaxf(pm0, vv0[j]);
                            pm1 = fmaxf(pm1, vv1[j]);
                        }
                    }
                    s_wmax[warp][2 * p] = fmaxf(s_wmax[warp][2 * p], pm0);
                    s_wmax[warp][2 * p + 1] = fmaxf(s_wmax[warp][2 * p + 1], pm1);
                }
            }
        }
    }

    __syncthreads();
    if (t < NQ) {
        float m = -1e30f;
#pragma unroll
        for (int w = 0; w < K1_WARPS; w++) m = fmaxf(m, s_wmax[w][t]);
        g_bmax[(size_t)blockIdx.x * NQ + t] = m;
    }
}

// ============================================================
// K1.5b: Z[q] = sum_n exp(l - M); M merged from g_bmax in-kernel
// (grid = NQ*32 blocks; part 0 publishes g_M[q])
// ============================================================
__global__ void k15b_z(int N, int nbmax) {
    int q = blockIdx.x >> 5, part = blockIdx.x & 31;
    int t = threadIdx.x;
    __shared__ float red[256];

    float m = -1e30f;
    for (int b = t; b < nbmax; b += 256)
        m = fmaxf(m, g_bmax[(size_t)b * NQ + q]);
    red[t] = m;
    __syncthreads();
    for (int s = 128; s > 0; s >>= 1) {
        if (t < s) red[t] = fmaxf(red[t], red[t + s]);
        __syncthreads();
    }
    float M = red[0];
    if (part == 0 && t == 0) g_M[q] = M;
    __syncthreads();

    const float* l = g_logits + (size_t)q * N;
    float s = 0.f;
    int n4 = N >> 2;
    int stride = 32 * 256;
    for (int i = part * 256 + t; i < n4; i += stride) {
        float4 v = *(const float4*)(l + 4 * i);
        s += __expf(v.x - M) + __expf(v.y - M) + __expf(v.z - M) + __expf(v.w - M);
    }
    for (int n = 4 * n4 + part * 256 + t; n < N; n += stride)
        s += __expf(l[n] - M);
    red[t] = s;
    __syncthreads();
    for (int st = 128; st > 0; st >>= 1) {
        if (t < st) red[t] += red[t + st];
        __syncthreads();
    }
    if (t == 0) atomicAdd(&g_Z[q], red[0]);
}

// ============================================================
// K2: persistent; acc[c] += g[n]*X[n][c] over block's tiles
//     g[n] = (1/NQ) * sum_q exp(l[q][n]-M_q)/Z_q   (R6 version)
// ============================================================
__global__ __launch_bounds__(256) void k2_wsum(const float* __restrict__ X,
                                               int N, int ntiles) {
    __shared__ float s_g[K2_TILE];
    __shared__ float s_m[NQ], s_iz[NQ];
    int t = threadIdx.x;
    if (t < NQ) { s_m[t] = g_M[t]; s_iz[t] = (1.0f / NQ) / g_Z[t]; }
    __syncthreads();

    float4 a = make_float4(0.f, 0.f, 0.f, 0.f);

    for (int tile = blockIdx.x; tile < ntiles; tile += gridDim.x) {
        int n0 = tile * K2_TILE;
        int nv = min(K2_TILE, N - n0);
        __syncthreads();   // previous tile's s_g reads complete
        if (t < K2_TILE) {
            float gs = 0.f;
            if (t < nv) {
                int n = n0 + t;
#pragma unroll
                for (int q = 0; q < NQ; q++)
                    gs = fmaf(__expf(g_logits[(size_t)q * N + n] - s_m[q]), s_iz[q], gs);
            }
            s_g[t] = gs;
        }
        __syncthreads();

        const float* xb = X + (size_t)n0 * C_DIM + 4 * t;
        int r = 0;
        for (; r + 8 <= nv; r += 8) {
            float4 x[8];
#pragma unroll
            for (int i = 0; i < 8; i++)
                x[i] = __ldcs((const float4*)(xb + (size_t)(r + i) * C_DIM));
#pragma unroll
            for (int i = 0; i < 8; i++) {
                float g = s_g[r + i];
                a.x = fmaf(g, x[i].x, a.x); a.y = fmaf(g, x[i].y, a.y);
                a.z = fmaf(g, x[i].z, a.z); a.w = fmaf(g, x[i].w, a.w);
            }
        }
        for (; r < nv; r++) {
            float4 x = __ldcs((const float4*)(xb + (size_t)r * C_DIM));
            float g = s_g[r];
            a.x = fmaf(g, x.x, a.x); a.y = fmaf(g, x.y, a.y);
            a.z = fmaf(g, x.z, a.z); a.w = fmaf(g, x.w, a.w);
        }
    }
    *(float4*)(g_partial + (size_t)blockIdx.x * C_DIM + 4 * t) = a;
}

// ============================================================
// K2.5: pooled[c] = sum_b partial[b][c]   (grid 64 x 128)
// ============================================================
__global__ void k25_reduce(int nblocks) {
    int cpart = blockIdx.x & 7;
    int bpart = blockIdx.x >> 3;
    int c = cpart * 128 + threadIdx.x;
    float s = 0.f;
    for (int bb = bpart; bb < nblocks; bb += 8)
        s += g_partial[(size_t)bb * C_DIM + c];
    atomicAdd(&g_pooled[c], s);
}

// ============================================================
// K3: out[j] = b[j] + sum_c pooled[c]*W[j][c]   (grid 128 x 256)
// ============================================================
__global__ __launch_bounds__(256) void k3_linear(const float* __restrict__ W,
                                                 const float* __restrict__ bias,
                                                 float* __restrict__ out) {
    int t = threadIdx.x;
    int j0 = blockIdx.x * 8;
    float4 p = *(const float4*)(g_pooled + 4 * t);
    float part[8];
#pragma unroll
    for (int j = 0; j < 8; j++) {
        const float4 w = *(const float4*)(W + (size_t)(j0 + j) * C_DIM + 4 * t);
        part[j] = fmaf(p.x, w.x, fmaf(p.y, w.y, fmaf(p.z, w.z, p.w * w.w)));
    }
#pragma unroll
    for (int j = 0; j < 8; j++)
#pragma unroll
        for (int off = 16; off; off >>= 1)
            part[j] += __shfl_xor_sync(0xffffffffu, part[j], off);
    __shared__ float s_p[8][8];
    int warp = t >> 5, lane = t & 31;
    if (lane == 0)
#pragma unroll
        for (int j = 0; j < 8; j++) s_p[warp][j] = part[j];
    __syncthreads();
    if (t < 8) {
        float s = 0.f;
#pragma unroll
        for (int w = 0; w < 8; w++) s += s_p[w][t];
        out[j0 + t] = s + bias[j0 + t];
    }
}

// ============================================================
extern "C" void kernel_launch(void* const* d_in, const int* in_sizes, int n_in,
                              void* d_out, int out_size) {
    const float* X = (const float*)d_in[0];
    const float* Q = (const float*)d_in[1];
    const float* W = (const float*)d_in[2];
    const float* b = (const float*)d_in[3];
    float* out = (float*)d_out;

    int N = in_sizes[0] / C_DIM;
    if (N > MAXN) N = MAXN;

    int k1_tiles = (N + K1_RPB - 1) / K1_RPB;
    int k2_tiles = (N + K2_TILE - 1) / K2_TILE;
    int k1_grid = (K1_GRID < k1_tiles) ? K1_GRID : k1_tiles;
    int k2_grid = (K2_GRID < k2_tiles) ? K2_GRID : k2_tiles;

    k0_prep<<<1, 128>>>(Q);
    k1_logits<<<k1_grid, 256>>>(X, N, k1_tiles);
    k15b_z<<<NQ * 32, 256>>>(N, k1_grid);
    k2_wsum<<<k2_grid, 256>>>(X, N, k2_tiles);
    k25_reduce<<<64, 128>>>(k2_grid);
    k3_linear<<<128, 256>>>(W, b, out);
}

// round 10
// speedup vs baseline: 1.3321x; 1.0564x over previous
#include <cuda_runtime.h>
#include <math.h>

#define C_DIM 1024
#define NQ 10            // gated queries (ref has NQ+1 = 11 query rows)
#define NP 5             // q-pairs
#define MAXN 100000
#define K1_RPW 4         // rows per warp per tile
#define K1_WARPS 8
#define K1_RPB (K1_RPW * K1_WARPS)   // 32 rows per tile
#define K1_GRID 296                  // persistent, 2 CTAs/SM (16 warps)
#define K2_TILE 128
#define K2_GRID 592                  // persistent, 4 CTAs/SM

typedef unsigned long long u64;

// ---- scratch (static device memory; no allocations) ----
__device__ u64   g_Qp[NP * C_DIM];                    // packed q-pair diffs [p][c]
__device__ float g_logits[(size_t)NQ * MAXN];         // [q][n], 4 MB
__device__ float g_bmax[(size_t)K1_GRID * NQ];        // per-block max partials
__device__ float g_M[NQ];                             // per-q max logit
__device__ float g_Z[NQ];                             // per-q softmax denom
__device__ float g_partial[(size_t)K2_GRID * C_DIM];  // pass-2 partials
__device__ float g_pooled[C_DIM];

// ---- packed f32x2 helpers ----
__device__ __forceinline__ u64 f2fma(u64 a, u64 b, u64 c) {
    u64 d;
    asm("fma.rn.f32x2 %0, %1, %2, %3;" : "=l"(d) : "l"(a), "l"(b), "l"(c));
    return d;
}
__device__ __forceinline__ u64 f2add(u64 a, u64 b) {
    u64 d;
    asm("add.rn.f32x2 %0, %1, %2;" : "=l"(d) : "l"(a), "l"(b));
    return d;
}
__device__ __forceinline__ u64 fdup(float x) {
    u64 d;
    asm("mov.b64 %0, {%1, %1};" : "=l"(d) : "f"(x));
    return d;
}
__device__ __forceinline__ u64 fpack(float lo, float hi) {
    u64 d;
    asm("mov.b64 %0, {%1, %2};" : "=l"(d) : "f"(lo), "f"(hi));
    return d;
}
__device__ __forceinline__ float f2lo(u64 v) { return __uint_as_float((unsigned)v); }
__device__ __forceinline__ float f2hi(u64 v) { return __uint_as_float((unsigned)(v >> 32)); }
__device__ __forceinline__ float f2sum(u64 v) { return f2lo(v) + f2hi(v); }
__device__ __forceinline__ u64 shfl_xor64(u64 v, int off) {
    unsigned lo = (unsigned)v, hi = (unsigned)(v >> 32);
    lo = __shfl_xor_sync(0xffffffffu, lo, off);
    hi = __shfl_xor_sync(0xffffffffu, hi, off);
    return (u64)lo | ((u64)hi << 32);
}

// ============================================================
// K0: normalize Q rows, build packed Qp pairs; init Z/pooled
// ============================================================
__global__ void k0_prep(const float* __restrict__ Q) {
    __shared__ float s_inv[NQ + 1];
    __shared__ float s_red[128];
    int t = threadIdx.x;
    for (int q = 0; q < NQ + 1; q++) {
        float ss = 0.f;
        for (int c = t; c < C_DIM; c += 128) {
            float v = Q[q * C_DIM + c];
            ss = fmaf(v, v, ss);
        }
        s_red[t] = ss;
        __syncthreads();
        for (int s = 64; s > 0; s >>= 1) {
            if (t < s) s_red[t] += s_red[t + s];
            __syncthreads();
        }
        if (t == 0) s_inv[q] = 1.0f / fmaxf(sqrtf(s_red[0]), 1e-12f);
        __syncthreads();
    }
    float invL = s_inv[NQ];
    for (int c = t; c < C_DIM; c += 128) {
        float ql = Q[NQ * C_DIM + c] * invL;
#pragma unroll
        for (int p = 0; p < NP; p++) {
            float lo = Q[(2 * p) * C_DIM + c] * s_inv[2 * p] - ql;
            float hi = Q[(2 * p + 1) * C_DIM + c] * s_inv[2 * p + 1] - ql;
            g_Qp[p * C_DIM + c] = fpack(lo, hi);
        }
    }
    if (t < NQ) g_Z[t] = 0.f;
    for (int c = t; c < C_DIM; c += 128) g_pooled[c] = 0.f;
}

// ============================================================
// K1: logits[q][n] = 100 * (Qd[q] . X[n]) / max(||X[n]||, eps)
// RPW=4, q-pair packed acc, 2 CTAs/SM, cross-tile pipelined
// prefetch, pair-merge warp reduction (110 shfl vs 288).
// ============================================================
__global__ __launch_bounds__(256, 2) void k1_logits(const float* __restrict__ X,
                                                    int N, int ntiles) {
    __shared__ u64 s_qp[NP * C_DIM];            // 40 KB
    __shared__ float s_wmax[K1_WARPS][NQ];
    int t = threadIdx.x;
    int warp = t >> 5, lane = t & 31;
    for (int i = t; i < NP * C_DIM; i += 256) s_qp[i] = g_Qp[i];
    if (t < K1_WARPS * NQ) ((float*)s_wmax)[t] = -1e30f;
    __syncthreads();

    bool hi16 = (lane & 16) != 0;

    // row offsets for first tile
    int ro[K1_RPW], ro_next[K1_RPW];
    {
        int row0 = blockIdx.x * K1_RPB + warp * K1_RPW;
#pragma unroll
        for (int j = 0; j < K1_RPW; j++) {
            int r = row0 + j;
            if (r > N - 1) r = N - 1;
            ro[j] = r * C_DIM + 2 * lane;
        }
    }

    // preload chunks 0,1 of first tile
    u64 A0[K1_RPW], A1[K1_RPW], B0[K1_RPW], B1[K1_RPW];
#pragma unroll
    for (int j = 0; j < K1_RPW; j++) {
        A0[j] = __ldcs((const u64*)(X + ro[j]));
        A1[j] = __ldcs((const u64*)(X + ro[j] + 64));
    }
#pragma unroll
    for (int j = 0; j < K1_RPW; j++) {
        B0[j] = __ldcs((const u64*)(X + ro[j] + 128));
        B1[j] = __ldcs((const u64*)(X + ro[j] + 192));
    }

    for (int tile = blockIdx.x; tile < ntiles; tile += gridDim.x) {
        int row0 = tile * K1_RPB + warp * K1_RPW;
        // next tile's row offsets (clamped; harmless if past end)
        {
            int row0n = (tile + gridDim.x) * K1_RPB + warp * K1_RPW;
#pragma unroll
            for (int j = 0; j < K1_RPW; j++) {
                int r = row0n + j;
                if (r > N - 1) r = N - 1;
                ro_next[j] = r * C_DIM + 2 * lane;
            }
        }

        u64 acc[K1_RPW][NP];
        u64 nacc[K1_RPW];
#pragma unroll
        for (int j = 0; j < K1_RPW; j++) {
            nacc[j] = 0ull;
#pragma unroll
            for (int p = 0; p < NP; p++) acc[j][p] = 0ull;
        }

#pragma unroll
        for (int kk = 0; kk < 8; kk++) {
            u64* x0 = (kk & 1) ? B0 : A0;
            u64* x1 = (kk & 1) ? B1 : A1;
            int cb = kk * 128 + 2 * lane;

            // ---- half 0: cols [cb, cb+1] ----
            {
                u64 xd[2 * K1_RPW];
#pragma unroll
                for (int j = 0; j < K1_RPW; j++) {
                    u64 x = x0[j];
                    xd[2 * j] = fdup(f2lo(x));
                    xd[2 * j + 1] = fdup(f2hi(x));
                    nacc[j] = f2fma(x, x, nacc[j]);
                }
                if (kk < 6) {
                    int nb = (kk + 2) * 128;
#pragma unroll
                    for (int j = 0; j < K1_RPW; j++)
                        x0[j] = __ldcs((const u64*)(X + ro[j] + nb));
                } else {
                    // cross-tile prefetch: chunk (kk-6) of next tile
                    int nb = (kk - 6) * 128;
#pragma unroll
                    for (int j = 0; j < K1_RPW; j++)
                        x0[j] = __ldcs((const u64*)(X + ro_next[j] + nb));
                }
#pragma unroll
                for (int p = 0; p < NP; p++) {
                    ulonglong2 qa = *(const ulonglong2*)&s_qp[p * C_DIM + cb];
#pragma unroll
                    for (int j = 0; j < K1_RPW; j++) {
                        acc[j][p] = f2fma(xd[2 * j], qa.x, acc[j][p]);
                        acc[j][p] = f2fma(xd[2 * j + 1], qa.y, acc[j][p]);
                    }
                }
            }
            // ---- half 1: cols [cb+64, cb+65] ----
            {
                u64 xd[2 * K1_RPW];
#pragma unroll
                for (int j = 0; j < K1_RPW; j++) {
                    u64 x = x1[j];
                    xd[2 * j] = fdup(f2lo(x));
                    xd[2 * j + 1] = fdup(f2hi(x));
                    nacc[j] = f2fma(x, x, nacc[j]);
                }
                if (kk < 6) {
                    int nb = (kk + 2) * 128;
#pragma unroll
                    for (int j = 0; j < K1_RPW; j++)
                        x1[j] = __ldcs((const u64*)(X + ro[j] + nb + 64));
                } else {
                    int nb = (kk - 6) * 128;
#pragma unroll
                    for (int j = 0; j < K1_RPW; j++)
                        x1[j] = __ldcs((const u64*)(X + ro_next[j] + nb + 64));
                }
#pragma unroll
                for (int p = 0; p < NP; p++) {
                    ulonglong2 qb = *(const ulonglong2*)&s_qp[p * C_DIM + cb + 64];
#pragma unroll
                    for (int j = 0; j < K1_RPW; j++) {
                        acc[j][p] = f2fma(xd[2 * j], qb.x, acc[j][p]);
                        acc[j][p] = f2fma(xd[2 * j + 1], qb.y, acc[j][p]);
                    }
                }
            }
        }

        // ---- pair-merge reduction (overlaps with next tile's loads) ----
        // norms packed so half-warp's rows match its acc rows: (n0,n2)/(n1,n3)
        u64 nmA = fpack(f2sum(nacc[0]), f2sum(nacc[2]));
        u64 nmB = fpack(f2sum(nacc[1]), f2sum(nacc[3]));

        // round xor16: merge row pairs -> half-warp owns rows {0,2} or {1,3}
        u64 A[NP], Bv[NP];
#pragma unroll
        for (int p = 0; p < NP; p++) {
            u64 keepA = hi16 ? acc[1][p] : acc[0][p];
            u64 sendA = hi16 ? acc[0][p] : acc[1][p];
            A[p] = f2add(keepA, shfl_xor64(sendA, 16));
            u64 keepB = hi16 ? acc[3][p] : acc[2][p];
            u64 sendB = hi16 ? acc[2][p] : acc[3][p];
            Bv[p] = f2add(keepB, shfl_xor64(sendB, 16));
        }
        u64 keepN = hi16 ? nmB : nmA;
        u64 sendN = hi16 ? nmA : nmB;
        u64 nm = f2add(keepN, shfl_xor64(sendN, 16));

        // rounds xor8..1: butterfly on 11 u64
#pragma unroll
        for (int off = 8; off; off >>= 1) {
            nm = f2add(nm, shfl_xor64(nm, off));
#pragma unroll
            for (int p = 0; p < NP; p++) {
                A[p] = f2add(A[p], shfl_xor64(A[p], off));
                Bv[p] = f2add(Bv[p], shfl_xor64(Bv[p], off));
            }
        }

        // stores + wmax: half-warp holds rows rA = row0 + (hi16?1:0), rB = rA+2
        int rA = row0 + (hi16 ? 1 : 0);
        int rB = rA + 2;
        float scA = 100.0f / fmaxf(sqrtf(f2lo(nm)), 1e-12f);
        float scB = 100.0f / fmaxf(sqrtf(f2hi(nm)), 1e-12f);
        bool vA = (rA < N), vB = (rB < N);
        bool storer = (lane == 0) || (lane == 16);
#pragma unroll
        for (int p = 0; p < NP; p++) {
            float a0 = f2lo(A[p]) * scA, a1 = f2hi(A[p]) * scA;
            float b0 = f2lo(Bv[p]) * scB, b1 = f2hi(Bv[p]) * scB;
            if (storer && vA) {
                g_logits[(size_t)(2 * p) * N + rA] = a0;
                g_logits[(size_t)(2 * p + 1) * N + rA] = a1;
            }
            if (storer && vB) {
                g_logits[(size_t)(2 * p) * N + rB] = b0;
                g_logits[(size_t)(2 * p + 1) * N + rB] = b1;
            }
            float m0 = fmaxf(vA ? a0 : -1e30f, vB ? b0 : -1e30f);
            float m1 = fmaxf(vA ? a1 : -1e30f, vB ? b1 : -1e30f);
            m0 = fmaxf(m0, __shfl_xor_sync(0xffffffffu, m0, 16));
            m1 = fmaxf(m1, __shfl_xor_sync(0xffffffffu, m1, 16));
            if (lane == 0) {
                s_wmax[warp][2 * p] = fmaxf(s_wmax[warp][2 * p], m0);
                s_wmax[warp][2 * p + 1] = fmaxf(s_wmax[warp][2 * p + 1], m1);
            }
        }

        // rotate: next tile's ro
#pragma unroll
        for (int j = 0; j < K1_RPW; j++) ro[j] = ro_next[j];
    }

    __syncthreads();
    if (t < NQ) {
        float m = -1e30f;
#pragma unroll
        for (int w = 0; w < K1_WARPS; w++) m = fmaxf(m, s_wmax[w][t]);
        g_bmax[(size_t)blockIdx.x * NQ + t] = m;
    }
}

// ============================================================
// K1.5b: Z[q] = sum_n exp(l - M); M merged from g_bmax in-kernel
// (grid = NQ*64 blocks; part 0 publishes g_M[q])
// ============================================================
__global__ void k15b_z(int N, int nbmax) {
    int q = blockIdx.x >> 6, part = blockIdx.x & 63;
    int t = threadIdx.x;
    __shared__ float red[256];

    float m = -1e30f;
    for (int b = t; b < nbmax; b += 256)
        m = fmaxf(m, g_bmax[(size_t)b * NQ + q]);
    red[t] = m;
    __syncthreads();
    for (int s = 128; s > 0; s >>= 1) {
        if (t < s) red[t] = fmaxf(red[t], red[t + s]);
        __syncthreads();
    }
    float M = red[0];
    if (part == 0 && t == 0) g_M[q] = M;
    __syncthreads();

    const float* l = g_logits + (size_t)q * N;
    float s = 0.f;
    int n4 = N >> 2;
    int stride = 64 * 256;
    for (int i = part * 256 + t; i < n4; i += stride) {
        float4 v = *(const float4*)(l + 4 * i);
        s += __expf(v.x - M) + __expf(v.y - M) + __expf(v.z - M) + __expf(v.w - M);
    }
    for (int n = 4 * n4 + part * 256 + t; n < N; n += stride)
        s += __expf(l[n] - M);
    red[t] = s;
    __syncthreads();
    for (int st = 128; st > 0; st >>= 1) {
        if (t < st) red[t] += red[t + st];
        __syncthreads();
    }
    if (t == 0) atomicAdd(&g_Z[q], red[0]);
}

// ============================================================
// K2: persistent; acc[c] += g[n]*X[n][c] over block's tiles
//     g[n] = (1/NQ) * sum_q exp(l[q][n]-M_q)/Z_q
// ============================================================
__global__ __launch_bounds__(256) void k2_wsum(const float* __restrict__ X,
                                               int N, int ntiles) {
    __shared__ float s_g[K2_TILE];
    __shared__ float s_m[NQ], s_iz[NQ];
    int t = threadIdx.x;
    if (t < NQ) { s_m[t] = g_M[t]; s_iz[t] = (1.0f / NQ) / g_Z[t]; }
    __syncthreads();

    float4 a = make_float4(0.f, 0.f, 0.f, 0.f);

    for (int tile = blockIdx.x; tile < ntiles; tile += gridDim.x) {
        int n0 = tile * K2_TILE;
        int nv = min(K2_TILE, N - n0);
        __syncthreads();   // previous tile's s_g reads complete
        if (t < K2_TILE) {
            float gs = 0.f;
            if (t < nv) {
                int n = n0 + t;
#pragma unroll
                for (int q = 0; q < NQ; q++)
                    gs = fmaf(__expf(g_logits[(size_t)q * N + n] - s_m[q]), s_iz[q], gs);
            }
            s_g[t] = gs;
        }
        __syncthreads();

        const float* xb = X + (size_t)n0 * C_DIM + 4 * t;
        int r = 0;
        for (; r + 8 <= nv; r += 8) {
            float4 x[8];
#pragma unroll
            for (int i = 0; i < 8; i++)
                x[i] = __ldcs((const float4*)(xb + (size_t)(r + i) * C_DIM));
#pragma unroll
            for (int i = 0; i < 8; i++) {
                float g = s_g[r + i];
                a.x = fmaf(g, x[i].x, a.x); a.y = fmaf(g, x[i].y, a.y);
                a.z = fmaf(g, x[i].z, a.z); a.w = fmaf(g, x[i].w, a.w);
            }
        }
        for (; r < nv; r++) {
            float4 x = __ldcs((const float4*)(xb + (size_t)r * C_DIM));
            float g = s_g[r];
            a.x = fmaf(g, x.x, a.x); a.y = fmaf(g, x.y, a.y);
            a.z = fmaf(g, x.z, a.z); a.w = fmaf(g, x.w, a.w);
        }
    }
    *(float4*)(g_partial + (size_t)blockIdx.x * C_DIM + 4 * t) = a;
}

// ============================================================
// K2.5: pooled[c] = sum_b partial[b][c]   (grid 64 x 128)
// ============================================================
__global__ void k25_reduce(int nblocks) {
    int cpart = blockIdx.x & 7;
    int bpart = blockIdx.x >> 3;
    int c = cpart * 128 + threadIdx.x;
    float s = 0.f;
    for (int bb = bpart; bb < nblocks; bb += 8)
        s += g_partial[(size_t)bb * C_DIM + c];
    atomicAdd(&g_pooled[c], s);
}

// ============================================================
// K3: out[j] = b[j] + sum_c pooled[c]*W[j][c]   (grid 128 x 256)
// ============================================================
__global__ __launch_bounds__(256) void k3_linear(const float* __restrict__ W,
                                                 const float* __restrict__ bias,
                                                 float* __restrict__ out) {
    int t = threadIdx.x;
    int j0 = blockIdx.x * 8;
    float4 p = *(const float4*)(g_pooled + 4 * t);
    float part[8];
#pragma unroll
    for (int j = 0; j < 8; j++) {
        const float4 w = *(const float4*)(W + (size_t)(j0 + j) * C_DIM + 4 * t);
        part[j] = fmaf(p.x, w.x, fmaf(p.y, w.y, fmaf(p.z, w.z, p.w * w.w)));
    }
#pragma unroll
    for (int j = 0; j < 8; j++)
#pragma unroll
        for (int off = 16; off; off >>= 1)
            part[j] += __shfl_xor_sync(0xffffffffu, part[j], off);
    __shared__ float s_p[8][8];
    int warp = t >> 5, lane = t & 31;
    if (lane == 0)
#pragma unroll
        for (int j = 0; j < 8; j++) s_p[warp][j] = part[j];
    __syncthreads();
    if (t < 8) {
        float s = 0.f;
#pragma unroll
        for (int w = 0; w < 8; w++) s += s_p[w][t];
        out[j0 + t] = s + bias[j0 + t];
    }
}

// ============================================================
extern "C" void kernel_launch(void* const* d_in, const int* in_sizes, int n_in,
                              void* d_out, int out_size) {
    const float* X = (const float*)d_in[0];
    const float* Q = (const float*)d_in[1];
    const float* W = (const float*)d_in[2];
    const float* b = (const float*)d_in[3];
    float* out = (float*)d_out;

    int N = in_sizes[0] / C_DIM;
    if (N > MAXN) N = MAXN;

    int k1_tiles = (N + K1_RPB - 1) / K1_RPB;
    int k2_tiles = (N + K2_TILE - 1) / K2_TILE;
    int k1_grid = (K1_GRID < k1_tiles) ? K1_GRID : k1_tiles;
    int k2_grid = (K2_GRID < k2_tiles) ? K2_GRID : k2_tiles;

    k0_prep<<<1, 128>>>(Q);
    k1_logits<<<k1_grid, 256>>>(X, N, k1_tiles);
    k15b_z<<<NQ * 64, 256>>>(N, k1_grid);
    k2_wsum<<<k2_grid, 256>>>(X, N, k2_tiles);
    k25_reduce<<<64, 128>>>(k2_grid);
    k3_linear<<<128, 256>>>(W, b, out);
}

// round 11
// speedup vs baseline: 1.3675x; 1.0266x over previous
#include <cuda_runtime.h>
#include <math.h>

#define C_DIM 1024
#define NQ 10            // gated queries (ref has NQ+1 = 11 query rows)
#define NP 5             // q-pairs
#define MAXN 100000
#define K1_RPW 4         // rows per warp per tile
#define K1_WARPS 8
#define K1_RPB (K1_RPW * K1_WARPS)   // 32 rows per tile
#define K1_GRID 296                  // persistent, 2 CTAs/SM (16 warps)
#define K2_TILE 128
#define K2_GRID 592                  // persistent, 4 CTAs/SM

typedef unsigned long long u64;

// ---- scratch (static device memory; no allocations) ----
__device__ u64   g_Qp[NP * C_DIM];                    // packed q-pair diffs [p][c]
__device__ float g_logits[(size_t)NQ * MAXN];         // [q][n], 4 MB
__device__ float g_bmax[(size_t)K1_GRID * NQ];        // per-block max partials
__device__ float g_M[NQ];                             // per-q max logit
__device__ float g_Z[NQ];                             // per-q softmax denom
__device__ float g_partial[(size_t)K2_GRID * C_DIM];  // pass-2 partials
__device__ float g_pooled[C_DIM];

// ---- packed f32x2 helpers ----
__device__ __forceinline__ u64 f2fma(u64 a, u64 b, u64 c) {
    u64 d;
    asm("fma.rn.f32x2 %0, %1, %2, %3;" : "=l"(d) : "l"(a), "l"(b), "l"(c));
    return d;
}
__device__ __forceinline__ u64 f2add(u64 a, u64 b) {
    u64 d;
    asm("add.rn.f32x2 %0, %1, %2;" : "=l"(d) : "l"(a), "l"(b));
    return d;
}
__device__ __forceinline__ u64 fdup(float x) {
    u64 d;
    asm("mov.b64 %0, {%1, %1};" : "=l"(d) : "f"(x));
    return d;
}
__device__ __forceinline__ u64 fpack(float lo, float hi) {
    u64 d;
    asm("mov.b64 %0, {%1, %2};" : "=l"(d) : "f"(lo), "f"(hi));
    return d;
}
__device__ __forceinline__ float f2lo(u64 v) { return __uint_as_float((unsigned)v); }
__device__ __forceinline__ float f2hi(u64 v) { return __uint_as_float((unsigned)(v >> 32)); }
__device__ __forceinline__ float f2sum(u64 v) { return f2lo(v) + f2hi(v); }
__device__ __forceinline__ u64 shfl_xor64(u64 v, int off) {
    unsigned lo = (unsigned)v, hi = (unsigned)(v >> 32);
    lo = __shfl_xor_sync(0xffffffffu, lo, off);
    hi = __shfl_xor_sync(0xffffffffu, hi, off);
    return (u64)lo | ((u64)hi << 32);
}

// ============================================================
// K0: normalize Q rows, build packed Qp pairs; init Z/pooled
// ============================================================
__global__ void k0_prep(const float* __restrict__ Q) {
    __shared__ float s_inv[NQ + 1];
    __shared__ float s_red[128];
    int t = threadIdx.x;
    for (int q = 0; q < NQ + 1; q++) {
        float ss = 0.f;
        for (int c = t; c < C_DIM; c += 128) {
            float v = Q[q * C_DIM + c];
            ss = fmaf(v, v, ss);
        }
        s_red[t] = ss;
        __syncthreads();
        for (int s = 64; s > 0; s >>= 1) {
            if (t < s) s_red[t] += s_red[t + s];
            __syncthreads();
        }
        if (t == 0) s_inv[q] = 1.0f / fmaxf(sqrtf(s_red[0]), 1e-12f);
        __syncthreads();
    }
    float invL = s_inv[NQ];
    for (int c = t; c < C_DIM; c += 128) {
        float ql = Q[NQ * C_DIM + c] * invL;
#pragma unroll
        for (int p = 0; p < NP; p++) {
            float lo = Q[(2 * p) * C_DIM + c] * s_inv[2 * p] - ql;
            float hi = Q[(2 * p + 1) * C_DIM + c] * s_inv[2 * p + 1] - ql;
            g_Qp[p * C_DIM + c] = fpack(lo, hi);
        }
    }
    if (t < NQ) g_Z[t] = 0.f;
    for (int c = t; c < C_DIM; c += 128) g_pooled[c] = 0.f;
}

// ============================================================
// K1: logits[q][n] = 100 * (Qd[q] . X[n]) / max(||X[n]||, eps)
// Balanced contiguous tile ranges per block; RPW=4 q-pair acc,
// 2 CTAs/SM, sequential cross-tile prefetch, pair-merge reduce.
// ============================================================
__global__ __launch_bounds__(256, 2) void k1_logits(const float* __restrict__ X,
                                                    int N, int ntiles) {
    __shared__ u64 s_qp[NP * C_DIM];            // 40 KB
    __shared__ float s_wmax[K1_WARPS][NQ];
    int t = threadIdx.x;
    int warp = t >> 5, lane = t & 31;
    for (int i = t; i < NP * C_DIM; i += 256) s_qp[i] = g_Qp[i];
    if (t < K1_WARPS * NQ) ((float*)s_wmax)[t] = -1e30f;
    __syncthreads();

    bool hi16 = (lane & 16) != 0;

    // balanced contiguous tile range for this block
    int tb0 = (int)((long long)blockIdx.x * ntiles / gridDim.x);
    int tb1 = (int)((long long)(blockIdx.x + 1) * ntiles / gridDim.x);

    // row offsets for first tile
    int ro[K1_RPW], ro_next[K1_RPW];
    {
        int row0 = tb0 * K1_RPB + warp * K1_RPW;
#pragma unroll
        for (int j = 0; j < K1_RPW; j++) {
            int r = row0 + j;
            if (r > N - 1) r = N - 1;
            ro[j] = r * C_DIM + 2 * lane;
        }
    }

    // preload chunks 0,1 of first tile
    u64 A0[K1_RPW], A1[K1_RPW], B0[K1_RPW], B1[K1_RPW];
#pragma unroll
    for (int j = 0; j < K1_RPW; j++) {
        A0[j] = __ldcs((const u64*)(X + ro[j]));
        A1[j] = __ldcs((const u64*)(X + ro[j] + 64));
    }
#pragma unroll
    for (int j = 0; j < K1_RPW; j++) {
        B0[j] = __ldcs((const u64*)(X + ro[j] + 128));
        B1[j] = __ldcs((const u64*)(X + ro[j] + 192));
    }

    for (int tile = tb0; tile < tb1; tile++) {
        int row0 = tile * K1_RPB + warp * K1_RPW;
        // next tile's row offsets (sequential; clamped)
        {
            int row0n = (tile + 1) * K1_RPB + warp * K1_RPW;
#pragma unroll
            for (int j = 0; j < K1_RPW; j++) {
                int r = row0n + j;
                if (r > N - 1) r = N - 1;
                ro_next[j] = r * C_DIM + 2 * lane;
            }
        }

        u64 acc[K1_RPW][NP];
        u64 nacc[K1_RPW];
#pragma unroll
        for (int j = 0; j < K1_RPW; j++) {
            nacc[j] = 0ull;
#pragma unroll
            for (int p = 0; p < NP; p++) acc[j][p] = 0ull;
        }

#pragma unroll
        for (int kk = 0; kk < 8; kk++) {
            u64* x0 = (kk & 1) ? B0 : A0;
            u64* x1 = (kk & 1) ? B1 : A1;
            int cb = kk * 128 + 2 * lane;

            // ---- half 0: cols [cb, cb+1] ----
            {
                u64 xd[2 * K1_RPW];
#pragma unroll
                for (int j = 0; j < K1_RPW; j++) {
                    u64 x = x0[j];
                    xd[2 * j] = fdup(f2lo(x));
                    xd[2 * j + 1] = fdup(f2hi(x));
                    nacc[j] = f2fma(x, x, nacc[j]);
                }
                if (kk < 6) {
                    int nb = (kk + 2) * 128;
#pragma unroll
                    for (int j = 0; j < K1_RPW; j++)
                        x0[j] = __ldcs((const u64*)(X + ro[j] + nb));
                } else {
                    int nb = (kk - 6) * 128;
#pragma unroll
                    for (int j = 0; j < K1_RPW; j++)
                        x0[j] = __ldcs((const u64*)(X + ro_next[j] + nb));
                }
#pragma unroll
                for (int p = 0; p < NP; p++) {
                    ulonglong2 qa = *(const ulonglong2*)&s_qp[p * C_DIM + cb];
#pragma unroll
                    for (int j = 0; j < K1_RPW; j++) {
                        acc[j][p] = f2fma(xd[2 * j], qa.x, acc[j][p]);
                        acc[j][p] = f2fma(xd[2 * j + 1], qa.y, acc[j][p]);
                    }
                }
            }
            // ---- half 1: cols [cb+64, cb+65] ----
            {
                u64 xd[2 * K1_RPW];
#pragma unroll
                for (int j = 0; j < K1_RPW; j++) {
                    u64 x = x1[j];
                    xd[2 * j] = fdup(f2lo(x));
                    xd[2 * j + 1] = fdup(f2hi(x));
                    nacc[j] = f2fma(x, x, nacc[j]);
                }
                if (kk < 6) {
                    int nb = (kk + 2) * 128;
#pragma unroll
                    for (int j = 0; j < K1_RPW; j++)
                        x1[j] = __ldcs((const u64*)(X + ro[j] + nb + 64));
                } else {
                    int nb = (kk - 6) * 128;
#pragma unroll
                    for (int j = 0; j < K1_RPW; j++)
                        x1[j] = __ldcs((const u64*)(X + ro_next[j] + nb + 64));
                }
#pragma unroll
                for (int p = 0; p < NP; p++) {
                    ulonglong2 qb = *(const ulonglong2*)&s_qp[p * C_DIM + cb + 64];
#pragma unroll
                    for (int j = 0; j < K1_RPW; j++) {
                        acc[j][p] = f2fma(xd[2 * j], qb.x, acc[j][p]);
                        acc[j][p] = f2fma(xd[2 * j + 1], qb.y, acc[j][p]);
                    }
                }
            }
        }

        // ---- pair-merge reduction (overlaps with next tile's loads) ----
        u64 nmA = fpack(f2sum(nacc[0]), f2sum(nacc[2]));
        u64 nmB = fpack(f2sum(nacc[1]), f2sum(nacc[3]));

        // round xor16: merge row pairs -> half-warp owns rows {0,2} or {1,3}
        u64 A[NP], Bv[NP];
#pragma unroll
        for (int p = 0; p < NP; p++) {
            u64 keepA = hi16 ? acc[1][p] : acc[0][p];
            u64 sendA = hi16 ? acc[0][p] : acc[1][p];
            A[p] = f2add(keepA, shfl_xor64(sendA, 16));
            u64 keepB = hi16 ? acc[3][p] : acc[2][p];
            u64 sendB = hi16 ? acc[2][p] : acc[3][p];
            Bv[p] = f2add(keepB, shfl_xor64(sendB, 16));
        }
        u64 keepN = hi16 ? nmB : nmA;
        u64 sendN = hi16 ? nmA : nmB;
        u64 nm = f2add(keepN, shfl_xor64(sendN, 16));

        // rounds xor8..1: butterfly on 11 u64
#pragma unroll
        for (int off = 8; off; off >>= 1) {
            nm = f2add(nm, shfl_xor64(nm, off));
#pragma unroll
            for (int p = 0; p < NP; p++) {
                A[p] = f2add(A[p], shfl_xor64(A[p], off));
                Bv[p] = f2add(Bv[p], shfl_xor64(Bv[p], off));
            }
        }

        // stores + wmax: half-warp holds rows rA = row0 + (hi16?1:0), rB = rA+2
        int rA = row0 + (hi16 ? 1 : 0);
        int rB = rA + 2;
        float scA = 100.0f / fmaxf(sqrtf(f2lo(nm)), 1e-12f);
        float scB = 100.0f / fmaxf(sqrtf(f2hi(nm)), 1e-12f);
        bool vA = (rA < N), vB = (rB < N);
        bool storer = (lane == 0) || (lane == 16);
#pragma unroll
        for (int p = 0; p < NP; p++) {
            float a0 = f2lo(A[p]) * scA, a1 = f2hi(A[p]) * scA;
            float b0 = f2lo(Bv[p]) * scB, b1 = f2hi(Bv[p]) * scB;
            if (storer && vA) {
                g_logits[(size_t)(2 * p) * N + rA] = a0;
                g_logits[(size_t)(2 * p + 1) * N + rA] = a1;
            }
            if (storer && vB) {
                g_logits[(size_t)(2 * p) * N + rB] = b0;
                g_logits[(size_t)(2 * p + 1) * N + rB] = b1;
            }
            float m0 = fmaxf(vA ? a0 : -1e30f, vB ? b0 : -1e30f);
            float m1 = fmaxf(vA ? a1 : -1e30f, vB ? b1 : -1e30f);
            m0 = fmaxf(m0, __shfl_xor_sync(0xffffffffu, m0, 16));
            m1 = fmaxf(m1, __shfl_xor_sync(0xffffffffu, m1, 16));
            if (lane == 0) {
                s_wmax[warp][2 * p] = fmaxf(s_wmax[warp][2 * p], m0);
                s_wmax[warp][2 * p + 1] = fmaxf(s_wmax[warp][2 * p + 1], m1);
            }
        }

        // rotate: next tile's ro
#pragma unroll
        for (int j = 0; j < K1_RPW; j++) ro[j] = ro_next[j];
    }

    __syncthreads();
    if (t < NQ) {
        float m = -1e30f;
#pragma unroll
        for (int w = 0; w < K1_WARPS; w++) m = fmaxf(m, s_wmax[w][t]);
        g_bmax[(size_t)blockIdx.x * NQ + t] = m;
    }
}

// ============================================================
// K1.5b: Z[q] = sum_n exp(l - M); M merged from g_bmax in-kernel
// (grid = NQ*64 blocks; part 0 publishes g_M[q])
// ============================================================
__global__ void k15b_z(int N, int nbmax) {
    int q = blockIdx.x >> 6, part = blockIdx.x & 63;
    int t = threadIdx.x;
    __shared__ float red[256];

    float m = -1e30f;
    for (int b = t; b < nbmax; b += 256)
        m = fmaxf(m, g_bmax[(size_t)b * NQ + q]);
    red[t] = m;
    __syncthreads();
    for (int s = 128; s > 0; s >>= 1) {
        if (t < s) red[t] = fmaxf(red[t], red[t + s]);
        __syncthreads();
    }
    float M = red[0];
    if (part == 0 && t == 0) g_M[q] = M;
    __syncthreads();

    const float* l = g_logits + (size_t)q * N;
    float s = 0.f;
    int n4 = N >> 2;
    int stride = 64 * 256;
    for (int i = part * 256 + t; i < n4; i += stride) {
        float4 v = *(const float4*)(l + 4 * i);
        s += __expf(v.x - M) + __expf(v.y - M) + __expf(v.z - M) + __expf(v.w - M);
    }
    for (int n = 4 * n4 + part * 256 + t; n < N; n += stride)
        s += __expf(l[n] - M);
    red[t] = s;
    __syncthreads();
    for (int st = 128; st > 0; st >>= 1) {
        if (t < st) red[t] += red[t + st];
        __syncthreads();
    }
    if (t == 0) atomicAdd(&g_Z[q], red[0]);
}

// ============================================================
// K2: balanced contiguous row range per block; chunked s_g gather
//     acc[c] += g[n]*X[n][c],  g[n] = (1/NQ) sum_q softmax
// ============================================================
__global__ __launch_bounds__(256) void k2_wsum(const float* __restrict__ X, int N) {
    __shared__ float s_g[K2_TILE];
    __shared__ float s_m[NQ], s_iz[NQ];
    int t = threadIdx.x;
    if (t < NQ) { s_m[t] = g_M[t]; s_iz[t] = (1.0f / NQ) / g_Z[t]; }
    __syncthreads();

    // balanced contiguous row range
    int r0 = (int)((long long)blockIdx.x * N / gridDim.x);
    int r1 = (int)((long long)(blockIdx.x + 1) * N / gridDim.x);

    float4 a = make_float4(0.f, 0.f, 0.f, 0.f);

    for (int n0 = r0; n0 < r1; n0 += K2_TILE) {
        int nv = min(K2_TILE, r1 - n0);
        __syncthreads();   // previous chunk's s_g reads complete
        if (t < nv) {
            int n = n0 + t;
            float gs = 0.f;
#pragma unroll
            for (int q = 0; q < NQ; q++)
                gs = fmaf(__expf(g_logits[(size_t)q * N + n] - s_m[q]), s_iz[q], gs);
            s_g[t] = gs;
        }
        __syncthreads();

        const float* xb = X + (size_t)n0 * C_DIM + 4 * t;
        int r = 0;
        for (; r + 8 <= nv; r += 8) {
            float4 x[8];
#pragma unroll
            for (int i = 0; i < 8; i++)
                x[i] = __ldcs((const float4*)(xb + (size_t)(r + i) * C_DIM));
#pragma unroll
            for (int i = 0; i < 8; i++) {
                float g = s_g[r + i];
                a.x = fmaf(g, x[i].x, a.x); a.y = fmaf(g, x[i].y, a.y);
                a.z = fmaf(g, x[i].z, a.z); a.w = fmaf(g, x[i].w, a.w);
            }
        }
        for (; r < nv; r++) {
            float4 x = __ldcs((const float4*)(xb + (size_t)r * C_DIM));
            float g = s_g[r];
            a.x = fmaf(g, x.x, a.x); a.y = fmaf(g, x.y, a.y);
            a.z = fmaf(g, x.z, a.z); a.w = fmaf(g, x.w, a.w);
        }
    }
    *(float4*)(g_partial + (size_t)blockIdx.x * C_DIM + 4 * t) = a;
}

// ============================================================
// K2.5: pooled[c] = sum_b partial[b][c]   (grid 64 x 128)
// ============================================================
__global__ void k25_reduce(int nblocks) {
    int cpart = blockIdx.x & 7;
    int bpart = blockIdx.x >> 3;
    int c = cpart * 128 + threadIdx.x;
    float s = 0.f;
    for (int bb = bpart; bb < nblocks; bb += 8)
        s += g_partial[(size_t)bb * C_DIM + c];
    atomicAdd(&g_pooled[c], s);
}

// ============================================================
// K3: out[j] = b[j] + sum_c pooled[c]*W[j][c]   (grid 128 x 256)
// ============================================================
__global__ __launch_bounds__(256) void k3_linear(const float* __restrict__ W,
                                                 const float* __restrict__ bias,
                                                 float* __restrict__ out) {
    int t = threadIdx.x;
    int j0 = blockIdx.x * 8;
    float4 p = *(const float4*)(g_pooled + 4 * t);
    float part[8];
#pragma unroll
    for (int j = 0; j < 8; j++) {
        const float4 w = *(const float4*)(W + (size_t)(j0 + j) * C_DIM + 4 * t);
        part[j] = fmaf(p.x, w.x, fmaf(p.y, w.y, fmaf(p.z, w.z, p.w * w.w)));
    }
#pragma unroll
    for (int j = 0; j < 8; j++)
#pragma unroll
        for (int off = 16; off; off >>= 1)
            part[j] += __shfl_xor_sync(0xffffffffu, part[j], off);
    __shared__ float s_p[8][8];
    int warp = t >> 5, lane = t & 31;
    if (lane == 0)
#pragma unroll
        for (int j = 0; j < 8; j++) s_p[warp][j] = part[j];
    __syncthreads();
    if (t < 8) {
        float s = 0.f;
#pragma unroll
        for (int w = 0; w < 8; w++) s += s_p[w][t];
        out[j0 + t] = s + bias[j0 + t];
    }
}

// ============================================================
extern "C" void kernel_launch(void* const* d_in, const int* in_sizes, int n_in,
                              void* d_out, int out_size) {
    const float* X = (const float*)d_in[0];
    const float* Q = (const float*)d_in[1];
    const float* W = (const float*)d_in[2];
    const float* b = (const float*)d_in[3];
    float* out = (float*)d_out;

    int N = in_sizes[0] / C_DIM;
    if (N > MAXN) N = MAXN;

    int k1_tiles = (N + K1_RPB - 1) / K1_RPB;
    int k1_grid = (K1_GRID < k1_tiles) ? K1_GRID : k1_tiles;
    int k2_grid = (K2_GRID < N) ? K2_GRID : N;

    k0_prep<<<1, 128>>>(Q);
    k1_logits<<<k1_grid, 256>>>(X, N, k1_tiles);
    k15b_z<<<NQ * 64, 256>>>(N, k1_grid);
    k2_wsum<<<k2_grid, 256>>>(X, N);
    k25_reduce<<<64, 128>>>(k2_grid);
    k3_linear<<<128, 256>>>(W, b, out);
}